// round 3
// baseline (speedup 1.0000x reference)
#include <cuda_runtime.h>
#include <math.h>
#include <stdint.h>

// ---------------- problem constants ----------------
#define BB    4
#define SS    2048
#define HIDC  768
#define NH    6
#define HD    64
#define AHSZ  384
#define KW    9
#define MROWS (BB*SS)      // 8192
#define NZ    (BB*NH)      // 24
#define HK    (NH*KW)      // 54

// ---------------- scratch (__device__ globals; no allocation allowed) ----------------
__device__ float g_q   [MROWS*AHSZ];
__device__ float g_k   [MROWS*AHSZ];
__device__ float g_v   [MROWS*AHSZ];
__device__ float g_dw  [MROWS*HIDC];
__device__ float g_ks  [MROWS*AHSZ];
__device__ float g_conv[MROWS*AHSZ];
__device__ float g_logits[MROWS*HK];
__device__ float g_mx  [NZ*SS];
__device__ float g_inv [NZ*SS];
__device__ float g_pv  [4*(size_t)MROWS*AHSZ];   // split-K partials for PV
// fallbacks in case harness out buffer only holds a subset of the tuple
__device__ float g_attn_fb[MROWS*AHSZ];
__device__ float g_sco_fb [(size_t)NZ*SS*SS];

enum { M_QKV = 0, M_NT = 1, M_MIX = 2, M_SCORES = 3, M_FILT = 4 };

// ---------------- big-tile SGEMM: 128x128, BK=16, 256 thr, 8x8 microtile ----------------
#define BM2 128
#define BN2 128
#define BK2 16

template <int MODE>
__global__ void __launch_bounds__(256) gemm2(
    const float* __restrict__ A0, const float* __restrict__ A1,
    const float* __restrict__ W0, const float* __restrict__ W1, const float* __restrict__ W2,
    const float* __restrict__ b0, const float* __restrict__ b1, const float* __restrict__ b2,
    float* C0, float* C1, float* C2,
    int Kdim, int lda, int ldw, int ldc,
    const float* __restrict__ mask)
{
    __shared__ float As[BK2][BM2 + 4];
    __shared__ float Bs[BK2][BN2 + 4];

    const int tid = threadIdx.x;
    const int tx  = tid & 15;       // n dir
    const int ty  = tid >> 4;       // m dir
    const int m0  = blockIdx.y * BM2;
    const int n0  = blockIdx.x * BN2;

    const float* A = A0;
    const float* Ae = A1;           // elementwise partner (FILT)
    const float* W = W0;
    const float* bias = b0;
    float* C = C0;
    const float* maskrow = nullptr;

    if constexpr (MODE == M_QKV) {
        const int z = blockIdx.z;
        W    = (z == 0) ? W0 : ((z == 1) ? W1 : W2);
        bias = (z == 0) ? b0 : ((z == 1) ? b1 : b2);
        C    = (z == 0) ? C0 : ((z == 1) ? C1 : C2);
    }
    if constexpr (MODE == M_MIX) {
        const int z = blockIdx.z;
        A    = z ? A1 : A0;
        W    = z ? W1 : W0;
        bias = z ? b1 : b0;
        C    = C0 + z * AHSZ;
    }
    if constexpr (MODE == M_SCORES) {
        const int z = blockIdx.z, b = z / NH, h = z % NH;
        A = A0 + (size_t)b * SS * AHSZ + h * HD;        // Q
        W = W0 + (size_t)b * SS * AHSZ + h * HD;        // K (NT access)
        C = C0 + (size_t)z * SS * SS;
        maskrow = mask + (size_t)b * SS;
        lda = AHSZ; ldw = AHSZ; ldc = SS; Kdim = HD;
    }

    // A loader: lane-major rows -> conflict-free transposed STS
    const int arow = tid & 127;
    const int acol = (tid >> 7) * 8;
    // B loader (NN style: QKV/MIX/FILT)
    const int bkr = tid >> 4;            // 0..15
    const int bnc = (tid & 15) * 8;      // 0..120
    // B loader (NT style: NT/SCORES)
    const int bnr = tid & 127;
    const int bkc = (tid >> 7) * 8;

    float acc[8][8];
#pragma unroll
    for (int i = 0; i < 8; i++)
#pragma unroll
        for (int j = 0; j < 8; j++) acc[i][j] = 0.f;

    for (int k0 = 0; k0 < Kdim; k0 += BK2) {
        // ---- load A tile (transposed into As) ----
        {
            const float* ap = &A[(size_t)(m0 + arow) * lda + k0 + acol];
            float4 x0 = *reinterpret_cast<const float4*>(ap);
            float4 x1 = *reinterpret_cast<const float4*>(ap + 4);
            if constexpr (MODE == M_FILT) {
                const float* ep = &Ae[(size_t)(m0 + arow) * lda + k0 + acol];
                float4 e0 = *reinterpret_cast<const float4*>(ep);
                float4 e1 = *reinterpret_cast<const float4*>(ep + 4);
                x0.x *= e0.x; x0.y *= e0.y; x0.z *= e0.z; x0.w *= e0.w;
                x1.x *= e1.x; x1.y *= e1.y; x1.z *= e1.z; x1.w *= e1.w;
            }
            As[acol + 0][arow] = x0.x; As[acol + 1][arow] = x0.y;
            As[acol + 2][arow] = x0.z; As[acol + 3][arow] = x0.w;
            As[acol + 4][arow] = x1.x; As[acol + 5][arow] = x1.y;
            As[acol + 6][arow] = x1.z; As[acol + 7][arow] = x1.w;
        }
        // ---- load B tile ----
        if constexpr (MODE == M_QKV || MODE == M_MIX) {
            const float* wp = &W[(size_t)(k0 + bkr) * ldw + n0 + bnc];
            float4 w0 = *reinterpret_cast<const float4*>(wp);
            float4 w1 = *reinterpret_cast<const float4*>(wp + 4);
            *reinterpret_cast<float4*>(&Bs[bkr][bnc])     = w0;
            *reinterpret_cast<float4*>(&Bs[bkr][bnc + 4]) = w1;
        } else if constexpr (MODE == M_FILT) {
#pragma unroll
            for (int j = 0; j < 8; j++) {
                const int n = bnc + j;
                Bs[bkr][n] = (n < HK) ? W[(size_t)(k0 + bkr) * HK + n] : 0.f;
            }
        } else {  // M_NT, M_SCORES : W accessed [n, k]
            const float* wp = &W[(size_t)(n0 + bnr) * ldw + k0 + bkc];
            float4 w0 = *reinterpret_cast<const float4*>(wp);
            float4 w1 = *reinterpret_cast<const float4*>(wp + 4);
            Bs[bkc + 0][bnr] = w0.x; Bs[bkc + 1][bnr] = w0.y;
            Bs[bkc + 2][bnr] = w0.z; Bs[bkc + 3][bnr] = w0.w;
            Bs[bkc + 4][bnr] = w1.x; Bs[bkc + 5][bnr] = w1.y;
            Bs[bkc + 6][bnr] = w1.z; Bs[bkc + 7][bnr] = w1.w;
        }
        __syncthreads();

#pragma unroll
        for (int kk = 0; kk < BK2; kk++) {
            float a[8], bv[8];
            float4 t;
            t = *reinterpret_cast<const float4*>(&As[kk][ty * 8]);
            a[0] = t.x; a[1] = t.y; a[2] = t.z; a[3] = t.w;
            t = *reinterpret_cast<const float4*>(&As[kk][ty * 8 + 4]);
            a[4] = t.x; a[5] = t.y; a[6] = t.z; a[7] = t.w;
            t = *reinterpret_cast<const float4*>(&Bs[kk][tx * 8]);
            bv[0] = t.x; bv[1] = t.y; bv[2] = t.z; bv[3] = t.w;
            t = *reinterpret_cast<const float4*>(&Bs[kk][tx * 8 + 4]);
            bv[4] = t.x; bv[5] = t.y; bv[6] = t.z; bv[7] = t.w;
#pragma unroll
            for (int i = 0; i < 8; i++)
#pragma unroll
                for (int j = 0; j < 8; j++) acc[i][j] += a[i] * bv[j];
        }
        __syncthreads();
    }

    // ---- epilogue ----
    if constexpr (MODE == M_FILT) {
#pragma unroll
        for (int i = 0; i < 8; i++) {
            const int m = m0 + ty * 8 + i;
#pragma unroll
            for (int j = 0; j < 8; j++) {
                const int n = tx * 8 + j;
                if (n < HK) C[(size_t)m * HK + n] = acc[i][j] + bias[n];
            }
        }
    } else if constexpr (MODE == M_SCORES) {
        float mk[8];
#pragma unroll
        for (int j = 0; j < 8; j++) mk[j] = maskrow[n0 + tx * 8 + j];
#pragma unroll
        for (int i = 0; i < 8; i++) {
            const int m = m0 + ty * 8 + i;
            float* crow = &C[(size_t)m * ldc + n0 + tx * 8];
            *reinterpret_cast<float4*>(crow) = make_float4(
                acc[i][0] * 0.125f + mk[0], acc[i][1] * 0.125f + mk[1],
                acc[i][2] * 0.125f + mk[2], acc[i][3] * 0.125f + mk[3]);
            *reinterpret_cast<float4*>(crow + 4) = make_float4(
                acc[i][4] * 0.125f + mk[4], acc[i][5] * 0.125f + mk[5],
                acc[i][6] * 0.125f + mk[6], acc[i][7] * 0.125f + mk[7]);
        }
    } else {
        float bj[8];
#pragma unroll
        for (int j = 0; j < 8; j++) bj[j] = bias[n0 + tx * 8 + j];
#pragma unroll
        for (int i = 0; i < 8; i++) {
            const int m = m0 + ty * 8 + i;
            float* crow = &C[(size_t)m * ldc + n0 + tx * 8];
            *reinterpret_cast<float4*>(crow) = make_float4(
                acc[i][0] + bj[0], acc[i][1] + bj[1], acc[i][2] + bj[2], acc[i][3] + bj[3]);
            *reinterpret_cast<float4*>(crow + 4) = make_float4(
                acc[i][4] + bj[4], acc[i][5] + bj[5], acc[i][6] + bj[6], acc[i][7] + bj[7]);
        }
    }
}

// ---------------- PV: partial = exp(scores - mx) @ V, split-K x4 ----------------
#define PVS 4
#define PVK (SS / PVS)   // 512

__global__ void __launch_bounds__(256) pv_k(const float* __restrict__ scores,
                                            const float* __restrict__ v,
                                            const float* __restrict__ mxv,
                                            float* __restrict__ partial)
{
    __shared__ float As[BK2][BM2 + 4];
    __shared__ float Bs[BK2][HD + 4];

    const int tid = threadIdx.x;
    const int tx = tid & 15, ty = tid >> 4;
    const int spz = blockIdx.x;                 // split index
    const int m0  = blockIdx.y * BM2;           // row-tile within SS
    const int z = blockIdx.z, b = z / NH, h = z % NH;

    const float* A  = scores + (size_t)z * SS * SS;
    const float* W  = v + (size_t)b * SS * AHSZ + h * HD;
    const float* mx = mxv + (size_t)z * SS;

    const int arow = tid & 127;
    const int acol = (tid >> 7) * 8;
    const float mxr = mx[m0 + arow];
    const int bkr = tid >> 4;
    const int bnc = (tid & 15) * 4;

    float acc[8][4];
#pragma unroll
    for (int i = 0; i < 8; i++)
#pragma unroll
        for (int j = 0; j < 4; j++) acc[i][j] = 0.f;

    const int kbase = spz * PVK;
    for (int k0 = kbase; k0 < kbase + PVK; k0 += BK2) {
        {
            const float* ap = &A[(size_t)(m0 + arow) * SS + k0 + acol];
            float4 x0 = *reinterpret_cast<const float4*>(ap);
            float4 x1 = *reinterpret_cast<const float4*>(ap + 4);
            As[acol + 0][arow] = __expf(x0.x - mxr);
            As[acol + 1][arow] = __expf(x0.y - mxr);
            As[acol + 2][arow] = __expf(x0.z - mxr);
            As[acol + 3][arow] = __expf(x0.w - mxr);
            As[acol + 4][arow] = __expf(x1.x - mxr);
            As[acol + 5][arow] = __expf(x1.y - mxr);
            As[acol + 6][arow] = __expf(x1.z - mxr);
            As[acol + 7][arow] = __expf(x1.w - mxr);
        }
        {
            const float4 w0 = *reinterpret_cast<const float4*>(&W[(size_t)(k0 + bkr) * AHSZ + bnc]);
            *reinterpret_cast<float4*>(&Bs[bkr][bnc]) = w0;
        }
        __syncthreads();

#pragma unroll
        for (int kk = 0; kk < BK2; kk++) {
            float a[8];
            float4 t;
            t = *reinterpret_cast<const float4*>(&As[kk][ty * 8]);
            a[0] = t.x; a[1] = t.y; a[2] = t.z; a[3] = t.w;
            t = *reinterpret_cast<const float4*>(&As[kk][ty * 8 + 4]);
            a[4] = t.x; a[5] = t.y; a[6] = t.z; a[7] = t.w;
            const float4 bv = *reinterpret_cast<const float4*>(&Bs[kk][tx * 4]);
#pragma unroll
            for (int i = 0; i < 8; i++) {
                acc[i][0] += a[i] * bv.x;
                acc[i][1] += a[i] * bv.y;
                acc[i][2] += a[i] * bv.z;
                acc[i][3] += a[i] * bv.w;
            }
        }
        __syncthreads();
    }

    float* P = partial + (size_t)spz * MROWS * AHSZ + (size_t)b * SS * AHSZ + h * HD;
#pragma unroll
    for (int i = 0; i < 8; i++) {
        const int m = m0 + ty * 8 + i;
        *reinterpret_cast<float4*>(&P[(size_t)m * AHSZ + tx * 4]) =
            make_float4(acc[i][0], acc[i][1], acc[i][2], acc[i][3]);
    }
}

__global__ void __launch_bounds__(256) pv_reduce_k(const float* __restrict__ partial,
                                                   const float* __restrict__ inv,
                                                   float* __restrict__ attn)
{
    const size_t idx = (size_t)blockIdx.x * 256 + threadIdx.x;   // < MROWS*AHSZ
    const int m = (int)(idx / AHSZ), c = (int)(idx % AHSZ);
    const int b = m >> 11, sl = m & (SS - 1);
    const int h = c >> 6;
    const size_t N = (size_t)MROWS * AHSZ;
    const float s = partial[idx] + partial[idx + N] + partial[idx + 2 * N] + partial[idx + 3 * N];
    attn[idx] = s * inv[(size_t)(b * NH + h) * SS + sl];
}

// ---------------- softmax row stats (max, 1/sum) over stored scores ----------------
__global__ void __launch_bounds__(256) softmax_stats_k(const float* __restrict__ scores)
{
    __shared__ float red[256];
    const size_t r = blockIdx.x;
    const float4* rv = reinterpret_cast<const float4*>(scores + r * SS);
    const int t = threadIdx.x;

    float v[8];
    float mx = -1e30f;
#pragma unroll
    for (int i = 0; i < 2; i++) {
        const float4 q4 = rv[t + i * 256];
        v[i * 4 + 0] = q4.x; v[i * 4 + 1] = q4.y; v[i * 4 + 2] = q4.z; v[i * 4 + 3] = q4.w;
        mx = fmaxf(mx, fmaxf(fmaxf(q4.x, q4.y), fmaxf(q4.z, q4.w)));
    }
    red[t] = mx;
    __syncthreads();
    for (int s = 128; s > 0; s >>= 1) {
        if (t < s) red[t] = fmaxf(red[t], red[t + s]);
        __syncthreads();
    }
    mx = red[0];
    __syncthreads();

    float sum = 0.f;
#pragma unroll
    for (int i = 0; i < 8; i++) sum += __expf(v[i] - mx);
    red[t] = sum;
    __syncthreads();
    for (int s = 128; s > 0; s >>= 1) {
        if (t < s) red[t] += red[t + s];
        __syncthreads();
    }
    if (t == 0) { g_mx[r] = mx; g_inv[r] = 1.f / red[0]; }
}

// ---------------- depthwise conv along S (groups=HID), output transposed to [b,s,c] ----------------
__global__ void __launch_bounds__(256) dwconv_k(const float* __restrict__ x,
                                                const float* __restrict__ dwk)
{
    const int s = blockIdx.x;
    const int b = blockIdx.y;
    for (int c = threadIdx.x; c < HIDC; c += 256) {
        float acc = 0.f;
#pragma unroll
        for (int tp = 0; tp < KW; tp++) {
            const int sp = s + tp - KW / 2;
            if (sp >= 0 && sp < SS)
                acc += x[((size_t)b * SS + sp) * HIDC + c] * dwk[c * KW + tp];
        }
        g_dw[((size_t)b * SS + s) * HIDC + c] = acc;
    }
}

// ---------------- softmax over K taps + windowed value conv ----------------
__global__ void __launch_bounds__(AHSZ) convout_k()
{
    const int m = blockIdx.x;
    const int b = m / SS;
    const int s = m % SS;
    __shared__ float filt[HK];
    const int t = threadIdx.x;   // 0..383

    if (t < NH) {
        float lg[KW];
        float mx = -1e30f;
#pragma unroll
        for (int i = 0; i < KW; i++) {
            lg[i] = g_logits[(size_t)m * HK + t * KW + i];
            mx = fmaxf(mx, lg[i]);
        }
        float sum = 0.f;
#pragma unroll
        for (int i = 0; i < KW; i++) { lg[i] = __expf(lg[i] - mx); sum += lg[i]; }
        const float is = 1.f / sum;
#pragma unroll
        for (int i = 0; i < KW; i++) filt[t * KW + i] = lg[i] * is;
    }
    __syncthreads();

    const int h = t / HD;
    float acc = 0.f;
#pragma unroll
    for (int tp = 0; tp < KW; tp++) {
        const int sp = s + tp - KW / 2;
        if (sp >= 0 && sp < SS)
            acc += g_v[((size_t)b * SS + sp) * AHSZ + t] * filt[h * KW + tp];
    }
    g_conv[(size_t)m * AHSZ + t] = acc;
}

// ---------------- launch ----------------
extern "C" void kernel_launch(void* const* d_in, const int* in_sizes, int n_in,
                              void* d_out, int out_size)
{
    const float* hidden = (const float*)d_in[0];
    const float* amask  = (const float*)d_in[1];
    const float* Wq = (const float*)d_in[2];  const float* bq = (const float*)d_in[3];
    const float* Wk = (const float*)d_in[4];  const float* bk = (const float*)d_in[5];
    const float* Wv = (const float*)d_in[6];  const float* bv = (const float*)d_in[7];
    const float* dwk = (const float*)d_in[8];
    const float* pw  = (const float*)d_in[9]; const float* sepb = (const float*)d_in[10];
    const float* Wak = (const float*)d_in[11]; const float* bak = (const float*)d_in[12];
    const float* Wsl = (const float*)d_in[13]; const float* bsl = (const float*)d_in[14];
    const float* Wcl = (const float*)d_in[15]; const float* bcl = (const float*)d_in[16];

    float *q, *k, *v, *dw, *ks, *cv, *lg, *pvp, *attn_fb, *sco_fb, *mxp, *invp;
    cudaGetSymbolAddress((void**)&q,   g_q);
    cudaGetSymbolAddress((void**)&k,   g_k);
    cudaGetSymbolAddress((void**)&v,   g_v);
    cudaGetSymbolAddress((void**)&dw,  g_dw);
    cudaGetSymbolAddress((void**)&ks,  g_ks);
    cudaGetSymbolAddress((void**)&cv,  g_conv);
    cudaGetSymbolAddress((void**)&lg,  g_logits);
    cudaGetSymbolAddress((void**)&pvp, g_pv);
    cudaGetSymbolAddress((void**)&attn_fb, g_attn_fb);
    cudaGetSymbolAddress((void**)&sco_fb,  g_sco_fb);
    cudaGetSymbolAddress((void**)&mxp,  g_mx);
    cudaGetSymbolAddress((void**)&invp, g_inv);

    float* outp = (float*)d_out;
    const size_t CTX_SZ = (size_t)MROWS * HIDC;
    const size_t ATT_OFF = CTX_SZ;
    const size_t ATT_SZ  = (size_t)MROWS * AHSZ;
    const size_t SCO_OFF = ATT_OFF + ATT_SZ;
    const size_t SCO_SZ  = (size_t)NZ * SS * SS;

    float* attnp = ((size_t)out_size >= ATT_OFF + ATT_SZ) ? outp + ATT_OFF : attn_fb;
    float* scop  = ((size_t)out_size >= SCO_OFF + SCO_SZ) ? outp + SCO_OFF : sco_fb;

    const dim3 blk(256);

    // 1) fused QKV projections: one launch, z selects W/bias/out
    gemm2<M_QKV><<<dim3(AHSZ / BN2, MROWS / BM2, 3), blk>>>(
        hidden, nullptr, Wq, Wk, Wv, bq, bk, bv, q, k, v,
        HIDC, HIDC, AHSZ, AHSZ, nullptr);

    // 2) scores = QK^T/8 + mask (batched over b,h)
    gemm2<M_SCORES><<<dim3(SS / BN2, SS / BM2, NZ), blk>>>(
        q, nullptr, k, nullptr, nullptr, nullptr, nullptr, nullptr,
        scop, nullptr, nullptr, 0, 0, 0, 0, amask);

    // 3) softmax row stats
    softmax_stats_k<<<NZ * SS, 256>>>(scop);

    // 4) PV split-K partials + reduce (applies 1/sum)
    pv_k<<<dim3(PVS, SS / BM2, NZ), blk>>>(scop, v, mxp, pvp);
    pv_reduce_k<<<(MROWS * AHSZ) / 256, 256>>>(pvp, invp, attnp);

    // 5) depthwise conv
    dwconv_k<<<dim3(SS, BB), 256>>>(hidden, dwk);

    // 6) pointwise: ks_out = dw @ pw^T + sep_bias (NT)
    gemm2<M_NT><<<dim3(AHSZ / BN2, MROWS / BM2, 1), blk>>>(
        dw, nullptr, pw, nullptr, nullptr, sepb, nullptr, nullptr,
        ks, nullptr, nullptr, HIDC, HIDC, HIDC, AHSZ, nullptr);

    // 7) filter logits: (ks*q) @ Wak + bak, N=54 guarded
    gemm2<M_FILT><<<dim3(1, MROWS / BM2, 1), blk>>>(
        ks, q, Wak, nullptr, nullptr, bak, nullptr, nullptr,
        lg, nullptr, nullptr, AHSZ, AHSZ, HK, HK, nullptr);

    // 8) tap softmax + windowed value conv
    convout_k<<<MROWS, AHSZ>>>();

    // 9) fused mix: context = [attn@Wsl+bsl | conv@Wcl+bcl], z selects path
    gemm2<M_MIX><<<dim3(AHSZ / BN2, MROWS / BM2, 2), blk>>>(
        attnp, cv, Wsl, Wcl, nullptr, bsl, bcl, nullptr,
        outp, nullptr, nullptr, AHSZ, AHSZ, AHSZ, HIDC, nullptr);
}

// round 4
// speedup vs baseline: 1.3755x; 1.3755x over previous
#include <cuda_runtime.h>
#include <math.h>
#include <stdint.h>

// ---------------- problem constants ----------------
#define BB    4
#define SS    2048
#define HIDC  768
#define NH    6
#define HD    64
#define AHSZ  384
#define KW    9
#define MROWS (BB*SS)      // 8192
#define NZ    (BB*NH)      // 24
#define HK    (NH*KW)      // 54

// ---------------- scratch ----------------
__device__ float g_q   [MROWS*AHSZ];
__device__ float g_k   [MROWS*AHSZ];
__device__ float g_v   [MROWS*AHSZ];
__device__ float g_dw  [MROWS*HIDC];
__device__ float g_ks  [MROWS*AHSZ];
__device__ float g_conv[MROWS*AHSZ];
__device__ float g_logits[MROWS*HK];
__device__ float g_attn_fb[MROWS*AHSZ];
__device__ float g_sco_fb [(size_t)NZ*SS*SS];

// ================= fused flash attention (tf32 mma.sync, max-free softmax) =================
// CTA: 64 q-rows, 256 threads (8 warps: wm in {0,1} x 32 rows, wn in {0..3} x 16 cols).
// Loop over 32 key-tiles of 64: S=QK^T/8+mask (write to gmem), P=exp(S), l+=rowsum,
// O += P*V.  Final: attn = O / l.

#define QS_LD 68
#define KS_LD 68
#define VS_LD 72
#define PS_LD 68
#define FSM_FLOATS (64*QS_LD + 64*KS_LD + 64*VS_LD + 64*PS_LD + SS + 64)

__device__ __forceinline__ float tf32r(float x) {
    asm("cvt.rna.tf32.f32 %0, %0;" : "+f"(x));
    return x;
}
__device__ __forceinline__ unsigned fu(float x) { return __float_as_uint(x); }

__device__ __forceinline__ void mma_tf32(float* d, const unsigned* a, const unsigned* b) {
    asm volatile(
        "mma.sync.aligned.m16n8k8.row.col.f32.tf32.tf32.f32 "
        "{%0,%1,%2,%3}, {%4,%5,%6,%7}, {%8,%9}, {%0,%1,%2,%3};"
        : "+f"(d[0]), "+f"(d[1]), "+f"(d[2]), "+f"(d[3])
        : "r"(a[0]), "r"(a[1]), "r"(a[2]), "r"(a[3]), "r"(b[0]), "r"(b[1]));
}

__global__ void __launch_bounds__(256, 2) fattn_k(
    const float* __restrict__ q, const float* __restrict__ k, const float* __restrict__ v,
    const float* __restrict__ amask, float* __restrict__ scores, float* __restrict__ attn)
{
    extern __shared__ float sm[];
    float* Qs   = sm;
    float* Ks   = Qs + 64 * QS_LD;
    float* Vs   = Ks + 64 * KS_LD;
    float* Ps   = Vs + 64 * VS_LD;
    float* msk  = Ps + 64 * PS_LD;
    float* lred = msk + SS;

    const int tid  = threadIdx.x;
    const int warp = tid >> 5, lane = tid & 31;
    const int lq = lane >> 2, lr = lane & 3;
    const int wm = warp & 1, wn = warp >> 1;
    const int m0 = blockIdx.x * 64;
    const int z = blockIdx.y, b = z / NH, h = z % NH;

    if (tid < 64) lred[tid] = 0.f;

    // mask row into smem
    {
        const float4* s4 = reinterpret_cast<const float4*>(amask + (size_t)b * SS);
        float4* d4 = reinterpret_cast<float4*>(msk);
        for (int i = tid; i < SS / 4; i += 256) d4[i] = s4[i];
    }
    // Q tile 64x64 -> tf32 in smem
    {
        const int r = tid >> 2, cb = (tid & 3) * 16;
        const float* qp = q + ((size_t)(b * SS + m0 + r)) * AHSZ + h * HD + cb;
#pragma unroll
        for (int u = 0; u < 4; u++) {
            float4 x = *reinterpret_cast<const float4*>(qp + u * 4);
            Qs[r * QS_LD + cb + u * 4 + 0] = tf32r(x.x);
            Qs[r * QS_LD + cb + u * 4 + 1] = tf32r(x.y);
            Qs[r * QS_LD + cb + u * 4 + 2] = tf32r(x.z);
            Qs[r * QS_LD + cb + u * 4 + 3] = tf32r(x.w);
        }
    }
    __syncthreads();

    float o[2][2][4];
#pragma unroll
    for (int i = 0; i < 2; i++)
#pragma unroll
        for (int j = 0; j < 2; j++)
#pragma unroll
            for (int r = 0; r < 4; r++) o[i][j][r] = 0.f;
    float lacc[2][2] = {{0.f, 0.f}, {0.f, 0.f}};

    const float* kbase = k + (size_t)b * SS * AHSZ + h * HD;
    const float* vbase = v + (size_t)b * SS * AHSZ + h * HD;
    float* sco = scores + (size_t)z * SS * SS;

    for (int kt = 0; kt < 32; kt++) {
        const int n0 = kt * 64;
        __syncthreads();
        // load K,V tiles -> tf32 smem
        {
            const int r = tid >> 2, cb = (tid & 3) * 16;
            const float* kp = kbase + (size_t)(n0 + r) * AHSZ + cb;
            const float* vp = vbase + (size_t)(n0 + r) * AHSZ + cb;
#pragma unroll
            for (int u = 0; u < 4; u++) {
                float4 xk = *reinterpret_cast<const float4*>(kp + u * 4);
                float4 xv = *reinterpret_cast<const float4*>(vp + u * 4);
                Ks[r * KS_LD + cb + u * 4 + 0] = tf32r(xk.x);
                Ks[r * KS_LD + cb + u * 4 + 1] = tf32r(xk.y);
                Ks[r * KS_LD + cb + u * 4 + 2] = tf32r(xk.z);
                Ks[r * KS_LD + cb + u * 4 + 3] = tf32r(xk.w);
                Vs[r * VS_LD + cb + u * 4 + 0] = tf32r(xv.x);
                Vs[r * VS_LD + cb + u * 4 + 1] = tf32r(xv.y);
                Vs[r * VS_LD + cb + u * 4 + 2] = tf32r(xv.z);
                Vs[r * VS_LD + cb + u * 4 + 3] = tf32r(xv.w);
            }
        }
        __syncthreads();

        // ---- S = Q K^T ----
        float c[2][2][4];
#pragma unroll
        for (int i = 0; i < 2; i++)
#pragma unroll
            for (int j = 0; j < 2; j++)
#pragma unroll
                for (int r = 0; r < 4; r++) c[i][j][r] = 0.f;

#pragma unroll
        for (int kk = 0; kk < 8; kk++) {
            unsigned a[2][4], bf[2][2];
#pragma unroll
            for (int i = 0; i < 2; i++) {
                const int row = wm * 32 + i * 16 + lq;
                const int col = kk * 8 + lr;
                a[i][0] = fu(Qs[row * QS_LD + col]);
                a[i][1] = fu(Qs[(row + 8) * QS_LD + col]);
                a[i][2] = fu(Qs[row * QS_LD + col + 4]);
                a[i][3] = fu(Qs[(row + 8) * QS_LD + col + 4]);
            }
#pragma unroll
            for (int j = 0; j < 2; j++) {
                const int key = wn * 16 + j * 8 + lq;
                const int d   = kk * 8 + lr;
                bf[j][0] = fu(Ks[key * KS_LD + d]);
                bf[j][1] = fu(Ks[key * KS_LD + d + 4]);
            }
#pragma unroll
            for (int i = 0; i < 2; i++)
#pragma unroll
                for (int j = 0; j < 2; j++) mma_tf32(c[i][j], a[i], bf[j]);
        }

        // ---- epilogue: scale+mask, write scores, exp, store P, accumulate l ----
#pragma unroll
        for (int i = 0; i < 2; i++) {
            const int row0 = wm * 32 + i * 16 + lq;
#pragma unroll
            for (int j = 0; j < 2; j++) {
                const int colL = wn * 16 + j * 8 + 2 * lr;
                const float mk0 = msk[n0 + colL], mk1 = msk[n0 + colL + 1];
                const float s0 = c[i][j][0] * 0.125f + mk0;
                const float s1 = c[i][j][1] * 0.125f + mk1;
                const float s2 = c[i][j][2] * 0.125f + mk0;
                const float s3 = c[i][j][3] * 0.125f + mk1;
                *reinterpret_cast<float2*>(&sco[(size_t)(m0 + row0) * SS + n0 + colL]) =
                    make_float2(s0, s1);
                *reinterpret_cast<float2*>(&sco[(size_t)(m0 + row0 + 8) * SS + n0 + colL]) =
                    make_float2(s2, s3);
                const float p0 = tf32r(__expf(s0));
                const float p1 = tf32r(__expf(s1));
                const float p2 = tf32r(__expf(s2));
                const float p3 = tf32r(__expf(s3));
                lacc[i][0] += p0 + p1;
                lacc[i][1] += p2 + p3;
                *reinterpret_cast<float2*>(&Ps[row0 * PS_LD + colL]) = make_float2(p0, p1);
                *reinterpret_cast<float2*>(&Ps[(row0 + 8) * PS_LD + colL]) = make_float2(p2, p3);
            }
        }
        __syncthreads();

        // ---- O += P V ----
#pragma unroll
        for (int kk = 0; kk < 8; kk++) {
            unsigned a[2][4], bf[2][2];
#pragma unroll
            for (int i = 0; i < 2; i++) {
                const int row = wm * 32 + i * 16 + lq;
                const int col = kk * 8 + lr;     // key
                a[i][0] = fu(Ps[row * PS_LD + col]);
                a[i][1] = fu(Ps[(row + 8) * PS_LD + col]);
                a[i][2] = fu(Ps[row * PS_LD + col + 4]);
                a[i][3] = fu(Ps[(row + 8) * PS_LD + col + 4]);
            }
#pragma unroll
            for (int j = 0; j < 2; j++) {
                const int dcol = wn * 16 + j * 8 + lq;
                const int key  = kk * 8 + lr;
                bf[j][0] = fu(Vs[key * VS_LD + dcol]);
                bf[j][1] = fu(Vs[(key + 4) * VS_LD + dcol]);
            }
#pragma unroll
            for (int i = 0; i < 2; i++)
#pragma unroll
                for (int j = 0; j < 2; j++) mma_tf32(o[i][j], a[i], bf[j]);
        }
    }

    // ---- reduce l across lanes/warps ----
    float l4[4] = {lacc[0][0], lacc[0][1], lacc[1][0], lacc[1][1]};
#pragma unroll
    for (int u = 0; u < 4; u++) {
        l4[u] += __shfl_xor_sync(0xFFFFFFFFu, l4[u], 1);
        l4[u] += __shfl_xor_sync(0xFFFFFFFFu, l4[u], 2);
    }
    __syncthreads();
    if (lr == 0) {
        atomicAdd(&lred[wm * 32 + lq],      l4[0]);
        atomicAdd(&lred[wm * 32 + lq + 8],  l4[1]);
        atomicAdd(&lred[wm * 32 + 16 + lq], l4[2]);
        atomicAdd(&lred[wm * 32 + 24 + lq], l4[3]);
    }
    __syncthreads();

    // ---- write attn = O / l ----
#pragma unroll
    for (int i = 0; i < 2; i++) {
        const int row0 = wm * 32 + i * 16 + lq;
        const float inv0 = 1.f / lred[row0];
        const float inv1 = 1.f / lred[row0 + 8];
#pragma unroll
        for (int j = 0; j < 2; j++) {
            const int dcol = wn * 16 + j * 8 + 2 * lr;
            float* ap = attn + ((size_t)(b * SS + m0 + row0)) * AHSZ + h * HD + dcol;
            *reinterpret_cast<float2*>(ap) =
                make_float2(o[i][j][0] * inv0, o[i][j][1] * inv0);
            float* ap2 = attn + ((size_t)(b * SS + m0 + row0 + 8)) * AHSZ + h * HD + dcol;
            *reinterpret_cast<float2*>(ap2) =
                make_float2(o[i][j][2] * inv1, o[i][j][3] * inv1);
        }
    }
}

// ================= round-2 proven FFMA GEMM (128x64, BK=16, 8x4 micro) =================
#define BM  128
#define BN  64
#define BKD 16
#define TM  8
#define TN  4
#define NTHR 256

enum { MODE_NN = 0, MODE_NT = 1, MODE_FILT = 2 };

template <int MODE>
__global__ void __launch_bounds__(NTHR) gemm_k(
    const float* __restrict__ Ab, const float* __restrict__ Ae,
    const float* __restrict__ Wb, const float* __restrict__ bias,
    float* __restrict__ Cb,
    int Kdim, int lda, int ldw, int ldc)
{
    __shared__ float As[BKD][BM + 4];
    __shared__ float Bs[BKD][BN + 4];

    const int tid = threadIdx.x;
    const int tx  = tid & 15;
    const int ty  = tid >> 4;
    const int m0  = blockIdx.y * BM;
    const int n0  = blockIdx.x * BN;

    float acc[TM][TN];
#pragma unroll
    for (int i = 0; i < TM; i++)
#pragma unroll
        for (int j = 0; j < TN; j++) acc[i][j] = 0.f;

    for (int k0 = 0; k0 < Kdim; k0 += BKD) {
#pragma unroll
        for (int i = 0; i < 2; i++) {
            const int f   = tid * 2 + i;
            const int row = f >> 2;
            const int col = (f & 3) * 4;
            float4 v4 = *reinterpret_cast<const float4*>(
                &Ab[(size_t)(m0 + row) * lda + k0 + col]);
            if constexpr (MODE == MODE_FILT) {
                const float4 e4 = *reinterpret_cast<const float4*>(
                    &Ae[(size_t)(m0 + row) * lda + k0 + col]);
                v4.x *= e4.x; v4.y *= e4.y; v4.z *= e4.z; v4.w *= e4.w;
            }
            As[col + 0][row] = v4.x;
            As[col + 1][row] = v4.y;
            As[col + 2][row] = v4.z;
            As[col + 3][row] = v4.w;
        }
        if constexpr (MODE == MODE_NN) {
            const int row = tid >> 4;
            const int col = (tid & 15) * 4;
            const float4 v4 = *reinterpret_cast<const float4*>(
                &Wb[(size_t)(k0 + row) * ldw + n0 + col]);
            *reinterpret_cast<float4*>(&Bs[row][col]) = v4;
        } else if constexpr (MODE == MODE_FILT) {
            const int row = tid >> 4;
            const int col = (tid & 15) * 4;
#pragma unroll
            for (int j = 0; j < 4; j++) {
                const int n = col + j;
                Bs[row][n] = (n < HK) ? Wb[(size_t)(k0 + row) * HK + n] : 0.f;
            }
        } else {  // NT
            const int col  = tid >> 2;
            const int rowb = (tid & 3) * 4;
            const float4 v4 = *reinterpret_cast<const float4*>(
                &Wb[(size_t)(n0 + col) * ldw + k0 + rowb]);
            Bs[rowb + 0][col] = v4.x;
            Bs[rowb + 1][col] = v4.y;
            Bs[rowb + 2][col] = v4.z;
            Bs[rowb + 3][col] = v4.w;
        }
        __syncthreads();

#pragma unroll
        for (int kk = 0; kk < BKD; kk++) {
            float a[TM], bv[TN];
            const float4 a0 = *reinterpret_cast<const float4*>(&As[kk][ty * TM]);
            const float4 a1 = *reinterpret_cast<const float4*>(&As[kk][ty * TM + 4]);
            a[0] = a0.x; a[1] = a0.y; a[2] = a0.z; a[3] = a0.w;
            a[4] = a1.x; a[5] = a1.y; a[6] = a1.z; a[7] = a1.w;
            const float4 b0 = *reinterpret_cast<const float4*>(&Bs[kk][tx * TN]);
            bv[0] = b0.x; bv[1] = b0.y; bv[2] = b0.z; bv[3] = b0.w;
#pragma unroll
            for (int i = 0; i < TM; i++)
#pragma unroll
                for (int j = 0; j < TN; j++) acc[i][j] += a[i] * bv[j];
        }
        __syncthreads();
    }

    if constexpr (MODE == MODE_FILT) {
#pragma unroll
        for (int i = 0; i < TM; i++) {
            const int m = m0 + ty * TM + i;
#pragma unroll
            for (int j = 0; j < TN; j++) {
                const int n = tx * TN + j;
                if (n < HK) Cb[(size_t)m * HK + n] = acc[i][j] + bias[n];
            }
        }
    } else {
#pragma unroll
        for (int i = 0; i < TM; i++) {
            const int m = m0 + ty * TM + i;
            float vj[TN];
#pragma unroll
            for (int j = 0; j < TN; j++) vj[j] = acc[i][j] + bias[n0 + tx * TN + j];
            *reinterpret_cast<float4*>(&Cb[(size_t)m * ldc + n0 + tx * TN]) =
                make_float4(vj[0], vj[1], vj[2], vj[3]);
        }
    }
}

// ---------------- depthwise conv ----------------
__global__ void __launch_bounds__(256) dwconv_k(const float* __restrict__ x,
                                                const float* __restrict__ dwk)
{
    const int s = blockIdx.x;
    const int b = blockIdx.y;
    for (int c = threadIdx.x; c < HIDC; c += 256) {
        float acc = 0.f;
#pragma unroll
        for (int tp = 0; tp < KW; tp++) {
            const int sp = s + tp - KW / 2;
            if (sp >= 0 && sp < SS)
                acc += x[((size_t)b * SS + sp) * HIDC + c] * dwk[c * KW + tp];
        }
        g_dw[((size_t)b * SS + s) * HIDC + c] = acc;
    }
}

// ---------------- tap softmax + windowed value conv ----------------
__global__ void __launch_bounds__(AHSZ) convout_k()
{
    const int m = blockIdx.x;
    const int b = m / SS;
    const int s = m % SS;
    __shared__ float filt[HK];
    const int t = threadIdx.x;

    if (t < NH) {
        float lg[KW];
        float mx = -1e30f;
#pragma unroll
        for (int i = 0; i < KW; i++) {
            lg[i] = g_logits[(size_t)m * HK + t * KW + i];
            mx = fmaxf(mx, lg[i]);
        }
        float sum = 0.f;
#pragma unroll
        for (int i = 0; i < KW; i++) { lg[i] = __expf(lg[i] - mx); sum += lg[i]; }
        const float is = 1.f / sum;
#pragma unroll
        for (int i = 0; i < KW; i++) filt[t * KW + i] = lg[i] * is;
    }
    __syncthreads();

    const int h = t / HD;
    float acc = 0.f;
#pragma unroll
    for (int tp = 0; tp < KW; tp++) {
        const int sp = s + tp - KW / 2;
        if (sp >= 0 && sp < SS)
            acc += g_v[((size_t)b * SS + sp) * AHSZ + t] * filt[h * KW + tp];
    }
    g_conv[(size_t)m * AHSZ + t] = acc;
}

// ---------------- launch ----------------
extern "C" void kernel_launch(void* const* d_in, const int* in_sizes, int n_in,
                              void* d_out, int out_size)
{
    const float* hidden = (const float*)d_in[0];
    const float* amask  = (const float*)d_in[1];
    const float* Wq = (const float*)d_in[2];  const float* bq = (const float*)d_in[3];
    const float* Wk = (const float*)d_in[4];  const float* bk = (const float*)d_in[5];
    const float* Wv = (const float*)d_in[6];  const float* bv = (const float*)d_in[7];
    const float* dwk = (const float*)d_in[8];
    const float* pw  = (const float*)d_in[9]; const float* sepb = (const float*)d_in[10];
    const float* Wak = (const float*)d_in[11]; const float* bak = (const float*)d_in[12];
    const float* Wsl = (const float*)d_in[13]; const float* bsl = (const float*)d_in[14];
    const float* Wcl = (const float*)d_in[15]; const float* bcl = (const float*)d_in[16];

    float *q, *k, *v, *dw, *ks, *cv, *lg, *attn_fb, *sco_fb;
    cudaGetSymbolAddress((void**)&q,   g_q);
    cudaGetSymbolAddress((void**)&k,   g_k);
    cudaGetSymbolAddress((void**)&v,   g_v);
    cudaGetSymbolAddress((void**)&dw,  g_dw);
    cudaGetSymbolAddress((void**)&ks,  g_ks);
    cudaGetSymbolAddress((void**)&cv,  g_conv);
    cudaGetSymbolAddress((void**)&lg,  g_logits);
    cudaGetSymbolAddress((void**)&attn_fb, g_attn_fb);
    cudaGetSymbolAddress((void**)&sco_fb,  g_sco_fb);

    float* outp = (float*)d_out;
    const size_t CTX_SZ = (size_t)MROWS * HIDC;
    const size_t ATT_OFF = CTX_SZ;
    const size_t ATT_SZ  = (size_t)MROWS * AHSZ;
    const size_t SCO_OFF = ATT_OFF + ATT_SZ;
    const size_t SCO_SZ  = (size_t)NZ * SS * SS;

    float* attnp = ((size_t)out_size >= ATT_OFF + ATT_SZ) ? outp + ATT_OFF : attn_fb;
    float* scop  = ((size_t)out_size >= SCO_OFF + SCO_SZ) ? outp + SCO_OFF : sco_fb;

    const dim3 blk(NTHR);

    // 1) Q, K, V projections
    {
        const dim3 grd(AHSZ / BN, MROWS / BM);
        gemm_k<MODE_NN><<<grd, blk>>>(hidden, nullptr, Wq, bq, q, HIDC, HIDC, AHSZ, AHSZ);
        gemm_k<MODE_NN><<<grd, blk>>>(hidden, nullptr, Wk, bk, k, HIDC, HIDC, AHSZ, AHSZ);
        gemm_k<MODE_NN><<<grd, blk>>>(hidden, nullptr, Wv, bv, v, HIDC, HIDC, AHSZ, AHSZ);
    }

    // 2) fused attention: scores write + max-free softmax + PV (tf32 mma)
    {
        const int smem = FSM_FLOATS * (int)sizeof(float);
        cudaFuncSetAttribute(fattn_k, cudaFuncAttributeMaxDynamicSharedMemorySize, smem);
        fattn_k<<<dim3(SS / 64, NZ), 256, smem>>>(q, k, v, amask, scop, attnp);
    }

    // 3) depthwise conv
    dwconv_k<<<dim3(SS, BB), 256>>>(hidden, dwk);

    // 4) pointwise: ks_out = dw @ pw^T + sep_bias (NT)
    gemm_k<MODE_NT><<<dim3(AHSZ / BN, MROWS / BM), blk>>>(
        dw, nullptr, pw, sepb, ks, HIDC, HIDC, HIDC, AHSZ);

    // 5) filter logits: (ks*q) @ Wak + bak (tiled, N=54 guarded)
    gemm_k<MODE_FILT><<<dim3(1, MROWS / BM), blk>>>(
        ks, q, Wak, bak, lg, AHSZ, AHSZ, HK, HK);

    // 6) tap softmax + windowed value conv
    convout_k<<<MROWS, AHSZ>>>();

    // 7) mix: context = [attn@Wsl+bsl | conv@Wcl+bcl]
    {
        const dim3 grd(AHSZ / BN, MROWS / BM);
        gemm_k<MODE_NN><<<grd, blk>>>(attnp, nullptr, Wsl, bsl, outp,        AHSZ, AHSZ, AHSZ, HIDC);
        gemm_k<MODE_NN><<<grd, blk>>>(cv,    nullptr, Wcl, bcl, outp + AHSZ, AHSZ, AHSZ, AHSZ, HIDC);
    }
}

// round 6
// speedup vs baseline: 2.5226x; 1.8340x over previous
#include <cuda_runtime.h>
#include <cuda_fp16.h>
#include <math.h>
#include <stdint.h>

// ---------------- problem constants ----------------
#define BB    4
#define SS    2048
#define HIDC  768
#define NH    6
#define HD    64
#define AHSZ  384
#define KW    9
#define MROWS (BB*SS)      // 8192
#define NZ    (BB*NH)      // 24
#define HK    (NH*KW)      // 54

// ---------------- scratch ----------------
__device__ float g_q   [MROWS*AHSZ];
__device__ float g_k   [MROWS*AHSZ];
__device__ float g_v   [MROWS*AHSZ];
__device__ float g_dw  [MROWS*HIDC];
__device__ float g_ks  [MROWS*AHSZ];
__device__ float g_conv[MROWS*AHSZ];
__device__ float g_logits[MROWS*HK];
__device__ float g_attn_fb[MROWS*AHSZ];
__device__ float g_sco_fb [(size_t)NZ*SS*SS];

// ---------------- mma helpers ----------------
__device__ __forceinline__ float tf32r(float x) {
    asm("cvt.rna.tf32.f32 %0, %0;" : "+f"(x));
    return x;
}
__device__ __forceinline__ unsigned fu(float x) { return __float_as_uint(x); }

__device__ __forceinline__ void mma_tf32(float* d, const unsigned* a, unsigned b0, unsigned b1) {
    asm volatile(
        "mma.sync.aligned.m16n8k8.row.col.f32.tf32.tf32.f32 "
        "{%0,%1,%2,%3}, {%4,%5,%6,%7}, {%8,%9}, {%0,%1,%2,%3};"
        : "+f"(d[0]), "+f"(d[1]), "+f"(d[2]), "+f"(d[3])
        : "r"(a[0]), "r"(a[1]), "r"(a[2]), "r"(a[3]), "r"(b0), "r"(b1));
}
__device__ __forceinline__ void mma_f16(float* d, const unsigned* a, unsigned b0, unsigned b1) {
    asm volatile(
        "mma.sync.aligned.m16n8k16.row.col.f32.f16.f16.f32 "
        "{%0,%1,%2,%3}, {%4,%5,%6,%7}, {%8,%9}, {%0,%1,%2,%3};"
        : "+f"(d[0]), "+f"(d[1]), "+f"(d[2]), "+f"(d[3])
        : "r"(a[0]), "r"(a[1]), "r"(a[2]), "r"(a[3]), "r"(b0), "r"(b1));
}
__device__ __forceinline__ unsigned pack_f16(float lo, float hi) {
    unsigned r;
    asm("cvt.rn.f16x2.f32 %0, %1, %2;" : "=r"(r) : "f"(hi), "f"(lo));
    return r;
}
__device__ __forceinline__ void ldsm4t(unsigned* r, unsigned addr) {
    asm volatile("ldmatrix.sync.aligned.m8n8.x4.trans.shared.b16 {%0,%1,%2,%3}, [%4];"
        : "=r"(r[0]), "=r"(r[1]), "=r"(r[2]), "=r"(r[3]) : "r"(addr));
}

// =================== fused flash attention v2 (fp16 PV) ===================
// 128 q-rows per CTA, 8 warps (warp w: rows w*16..w*16+15, all 64 keys of each kt).
// Q fragments register-resident. S = QK^T in tf32 mma. P = exp(S) packed to fp16
// in registers (FA2 repack); PV in fp16 mma with ldmatrix.trans V frags.
#define QS_P 68      // Q stage pitch (floats)
#define KS_P 68      // K tile pitch (floats)
#define VB_P 72      // V tile pitch (halves)
#define FA_UNION_F (128*QS_P)
#define FA_SMEM_F  (FA_UNION_F + SS)

__global__ void __launch_bounds__(256, 2) fattn_k(
    const float* __restrict__ q, const float* __restrict__ k, const float* __restrict__ v,
    const float* __restrict__ amask, float* __restrict__ scores, float* __restrict__ attn)
{
    extern __shared__ float sm[];
    float* Qs = sm;                               // [128][QS_P]
    float* Ks = sm;                               // [64][KS_P] (overlays Qs)
    __half* Vb = (__half*)(sm + 64 * KS_P);       // [64][VB_P]
    float* msk = sm + FA_UNION_F;                 // [SS]

    const int tid  = threadIdx.x;
    const int w    = tid >> 5, lane = tid & 31;
    const int lq   = lane >> 2, lr = lane & 3;
    const int m0   = blockIdx.x * 128;
    const int z    = blockIdx.y, b = z / NH, h = z % NH;
    const int row0 = w * 16 + lq;

    // mask into smem
    {
        const float4* s4 = reinterpret_cast<const float4*>(amask + (size_t)b * SS);
        float4* d4 = reinterpret_cast<float4*>(msk);
        for (int i = tid; i < SS / 4; i += 256) d4[i] = s4[i];
    }
    // stage Q (tf32) then lift fragments to registers
    {
        const int r = tid >> 1, cb = (tid & 1) * 32;
        const float* qp = q + ((size_t)(b * SS + m0 + r)) * AHSZ + h * HD + cb;
#pragma unroll
        for (int u = 0; u < 8; u++) {
            float4 x = *reinterpret_cast<const float4*>(qp + u * 4);
            x.x = tf32r(x.x); x.y = tf32r(x.y); x.z = tf32r(x.z); x.w = tf32r(x.w);
            *reinterpret_cast<float4*>(&Qs[r * QS_P + cb + u * 4]) = x;
        }
    }
    __syncthreads();

    unsigned Qa[8][4];
#pragma unroll
    for (int kk = 0; kk < 8; kk++) {
        Qa[kk][0] = fu(Qs[row0 * QS_P + kk * 8 + lr]);
        Qa[kk][1] = fu(Qs[(row0 + 8) * QS_P + kk * 8 + lr]);
        Qa[kk][2] = fu(Qs[row0 * QS_P + kk * 8 + lr + 4]);
        Qa[kk][3] = fu(Qs[(row0 + 8) * QS_P + kk * 8 + lr + 4]);
    }
    __syncthreads();   // Q region about to be overwritten by K/V

    float o[8][4];
#pragma unroll
    for (int d = 0; d < 8; d++)
#pragma unroll
        for (int r = 0; r < 4; r++) o[d][r] = 0.f;
    float lacc0 = 0.f, lacc1 = 0.f;

    const float* kbase = k + (size_t)b * SS * AHSZ + h * HD;
    const float* vbase = v + (size_t)b * SS * AHSZ + h * HD;
    float* sco = scores + (size_t)z * SS * SS;

    // lane-constant part of ldmatrix address
    const int msel = lane >> 3, mrow = lane & 7;
    const unsigned vb_base = (unsigned)__cvta_generic_to_shared(Vb)
        + (unsigned)((((msel & 1) * 8 + mrow) * VB_P + (msel >> 1) * 8) * 2);

    for (int kt = 0; kt < 32; kt++) {
        const int n0 = kt * 64;
        // ---- load K (tf32) and V (fp16) tiles ----
        {
            const int r = tid >> 2, cb = (tid & 3) * 16;
            const float* kp = kbase + (size_t)(n0 + r) * AHSZ + cb;
            const float* vp = vbase + (size_t)(n0 + r) * AHSZ + cb;
#pragma unroll
            for (int u = 0; u < 4; u++) {
                float4 xk = *reinterpret_cast<const float4*>(kp + u * 4);
                xk.x = tf32r(xk.x); xk.y = tf32r(xk.y); xk.z = tf32r(xk.z); xk.w = tf32r(xk.w);
                *reinterpret_cast<float4*>(&Ks[r * KS_P + cb + u * 4]) = xk;
                float4 xv = *reinterpret_cast<const float4*>(vp + u * 4);
                unsigned* vd = reinterpret_cast<unsigned*>(&Vb[r * VB_P + cb + u * 4]);
                vd[0] = pack_f16(xv.x, xv.y);
                vd[1] = pack_f16(xv.z, xv.w);
            }
        }
        __syncthreads();

        // ---- per 16-key chunk: S (2 n8 tiles) -> scores/exp/pack -> PV ----
#pragma unroll
        for (int t = 0; t < 4; t++) {
            float c[2][4];
#pragma unroll
            for (int jj = 0; jj < 2; jj++)
#pragma unroll
                for (int r = 0; r < 4; r++) c[jj][r] = 0.f;

            const int key0 = 2 * t * 8 + lq;       // tile 2t B row
            const int key1 = key0 + 8;             // tile 2t+1
#pragma unroll
            for (int kk = 0; kk < 8; kk++) {
                const unsigned b00 = fu(Ks[key0 * KS_P + kk * 8 + lr]);
                const unsigned b01 = fu(Ks[key0 * KS_P + kk * 8 + lr + 4]);
                const unsigned b10 = fu(Ks[key1 * KS_P + kk * 8 + lr]);
                const unsigned b11 = fu(Ks[key1 * KS_P + kk * 8 + lr + 4]);
                mma_tf32(c[0], Qa[kk], b00, b01);
                mma_tf32(c[1], Qa[kk], b10, b11);
            }

            unsigned pa[4];
#pragma unroll
            for (int jj = 0; jj < 2; jj++) {
                const int colL = (2 * t + jj) * 8 + 2 * lr;
                const float mk0 = msk[n0 + colL], mk1 = msk[n0 + colL + 1];
                const float s0 = c[jj][0] * 0.125f + mk0;
                const float s1 = c[jj][1] * 0.125f + mk1;
                const float s2 = c[jj][2] * 0.125f + mk0;
                const float s3 = c[jj][3] * 0.125f + mk1;
                *reinterpret_cast<float2*>(&sco[(size_t)(m0 + row0) * SS + n0 + colL]) =
                    make_float2(s0, s1);
                *reinterpret_cast<float2*>(&sco[(size_t)(m0 + row0 + 8) * SS + n0 + colL]) =
                    make_float2(s2, s3);
                const float p0 = __expf(s0), p1 = __expf(s1);
                const float p2 = __expf(s2), p3 = __expf(s3);
                lacc0 += p0 + p1;
                lacc1 += p2 + p3;
                pa[jj * 2 + 0] = pack_f16(p0, p1);
                pa[jj * 2 + 1] = pack_f16(p2, p3);
            }
            // pa: [0]=tile2t rows lq, [1]=tile2t rows lq+8, [2]=tile2t+1 lq, [3]=tile2t+1 lq+8
            // matches fp16 m16n8k16 A-fragment (FA2 repack)

            // ---- PV for this 16-key chunk (fp16) ----
            const unsigned vaddr_t = vb_base + (unsigned)(16 * t * VB_P * 2);
#pragma unroll
            for (int dp = 0; dp < 4; dp++) {
                unsigned vb[4];
                ldsm4t(vb, vaddr_t + (unsigned)(dp * 32));
                mma_f16(o[2 * dp],     pa, vb[0], vb[1]);
                mma_f16(o[2 * dp + 1], pa, vb[2], vb[3]);
            }
        }
        __syncthreads();
    }

    // ---- normalize & write attn ----
    float l0 = lacc0, l1 = lacc1;
    l0 += __shfl_xor_sync(0xFFFFFFFFu, l0, 1);
    l0 += __shfl_xor_sync(0xFFFFFFFFu, l0, 2);
    l1 += __shfl_xor_sync(0xFFFFFFFFu, l1, 1);
    l1 += __shfl_xor_sync(0xFFFFFFFFu, l1, 2);
    const float inv0 = 1.f / l0, inv1 = 1.f / l1;

#pragma unroll
    for (int d = 0; d < 8; d++) {
        const int col = h * HD + d * 8 + 2 * lr;
        *reinterpret_cast<float2*>(&attn[((size_t)(b * SS + m0 + row0)) * AHSZ + col]) =
            make_float2(o[d][0] * inv0, o[d][1] * inv0);
        *reinterpret_cast<float2*>(&attn[((size_t)(b * SS + m0 + row0 + 8)) * AHSZ + col]) =
            make_float2(o[d][2] * inv1, o[d][3] * inv1);
    }
}

// =================== tf32 tensor GEMM: 128x64x32 tile ===================
enum { T_QKV = 0, T_NT = 1, T_MIX = 2, T_FILT = 3 };
#define AS_P 36
#define WS_P 72

template <int MODE>
__global__ void __launch_bounds__(256, 4) tgemm(
    const float* __restrict__ A0, const float* __restrict__ A1, const float* __restrict__ Ae,
    const float* __restrict__ W0, const float* __restrict__ W1, const float* __restrict__ W2,
    const float* __restrict__ b0p, const float* __restrict__ b1p, const float* __restrict__ b2p,
    float* C0, float* C1, float* C2,
    int Kdim, int lda, int ldw, int ldc)
{
    __shared__ float As[128 * AS_P];
    __shared__ float Ws[32 * WS_P];

    const int tid = threadIdx.x;
    const int w = tid >> 5, lane = tid & 31;
    const int lq = lane >> 2, lr = lane & 3;
    const int m0 = blockIdx.y * 128;
    const int n0 = blockIdx.x * 64;

    const float* A = A0;
    const float* W = W0;
    const float* bias = b0p;
    float* C = C0;
    if constexpr (MODE == T_QKV) {
        const int z = blockIdx.z;
        W    = (z == 0) ? W0 : ((z == 1) ? W1 : W2);
        bias = (z == 0) ? b0p : ((z == 1) ? b1p : b2p);
        C    = (z == 0) ? C0 : ((z == 1) ? C1 : C2);
    }
    if constexpr (MODE == T_MIX) {
        const int z = blockIdx.z;
        A = z ? A1 : A0;
        W = z ? W1 : W0;
        bias = z ? b1p : b0p;
        C = C0 + z * AHSZ;
    }

    float c[8][4];
#pragma unroll
    for (int j = 0; j < 8; j++)
#pragma unroll
        for (int r = 0; r < 4; r++) c[j][r] = 0.f;

    const int ar = tid >> 1, acb = (tid & 1) * 16;

    for (int k0 = 0; k0 < Kdim; k0 += 32) {
        // ---- stage A (tf32) ----
        {
            const float* ap = &A[(size_t)(m0 + ar) * lda + k0 + acb];
#pragma unroll
            for (int u = 0; u < 4; u++) {
                float4 x = *reinterpret_cast<const float4*>(ap + u * 4);
                if constexpr (MODE == T_FILT) {
                    const float4 e = *reinterpret_cast<const float4*>(
                        &Ae[(size_t)(m0 + ar) * lda + k0 + acb + u * 4]);
                    x.x *= e.x; x.y *= e.y; x.z *= e.z; x.w *= e.w;
                }
                x.x = tf32r(x.x); x.y = tf32r(x.y); x.z = tf32r(x.z); x.w = tf32r(x.w);
                *reinterpret_cast<float4*>(&As[ar * AS_P + acb + u * 4]) = x;
            }
        }
        // ---- stage W (tf32), layout Ws[k][n] ----
        if constexpr (MODE == T_QKV || MODE == T_MIX) {
            const int kk = tid >> 3, nb = (tid & 7) * 8;
            const float* wp = &W[(size_t)(k0 + kk) * ldw + n0 + nb];
#pragma unroll
            for (int u = 0; u < 2; u++) {
                float4 x = *reinterpret_cast<const float4*>(wp + u * 4);
                x.x = tf32r(x.x); x.y = tf32r(x.y); x.z = tf32r(x.z); x.w = tf32r(x.w);
                *reinterpret_cast<float4*>(&Ws[kk * WS_P + nb + u * 4]) = x;
            }
        } else if constexpr (MODE == T_NT) {
            const int nn = tid >> 2, kb = (tid & 3) * 8;
            const float* wp = &W[(size_t)(n0 + nn) * ldw + k0 + kb];
#pragma unroll
            for (int u = 0; u < 2; u++) {
                float4 x = *reinterpret_cast<const float4*>(wp + u * 4);
                Ws[(kb + u * 4 + 0) * WS_P + nn] = tf32r(x.x);
                Ws[(kb + u * 4 + 1) * WS_P + nn] = tf32r(x.y);
                Ws[(kb + u * 4 + 2) * WS_P + nn] = tf32r(x.z);
                Ws[(kb + u * 4 + 3) * WS_P + nn] = tf32r(x.w);
            }
        } else {  // T_FILT: W is [K][HK], guard n<HK
            const int kk = tid >> 3, nb = (tid & 7) * 8;
#pragma unroll
            for (int j = 0; j < 8; j++) {
                const int n = nb + j;
                Ws[kk * WS_P + n] = (n < HK) ? tf32r(W[(size_t)(k0 + kk) * HK + n]) : 0.f;
            }
        }
        __syncthreads();

#pragma unroll
        for (int ks = 0; ks < 4; ks++) {
            unsigned af[4];
            af[0] = fu(As[(w * 16 + lq) * AS_P + ks * 8 + lr]);
            af[1] = fu(As[(w * 16 + lq + 8) * AS_P + ks * 8 + lr]);
            af[2] = fu(As[(w * 16 + lq) * AS_P + ks * 8 + lr + 4]);
            af[3] = fu(As[(w * 16 + lq + 8) * AS_P + ks * 8 + lr + 4]);
#pragma unroll
            for (int j = 0; j < 8; j++) {
                const unsigned bb0 = fu(Ws[(ks * 8 + lr) * WS_P + j * 8 + lq]);
                const unsigned bb1 = fu(Ws[(ks * 8 + lr + 4) * WS_P + j * 8 + lq]);
                mma_tf32(c[j], af, bb0, bb1);
            }
        }
        __syncthreads();
    }

    // ---- epilogue ----
    const int rowA = m0 + w * 16 + lq;
#pragma unroll
    for (int j = 0; j < 8; j++) {
        const int n = n0 + j * 8 + 2 * lr;
        if constexpr (MODE == T_FILT) {
            if (n + 1 >= HK) continue;
            const float bj0 = bias[n], bj1 = bias[n + 1];
            *reinterpret_cast<float2*>(&C[(size_t)rowA * HK + n]) =
                make_float2(c[j][0] + bj0, c[j][1] + bj1);
            *reinterpret_cast<float2*>(&C[(size_t)(rowA + 8) * HK + n]) =
                make_float2(c[j][2] + bj0, c[j][3] + bj1);
        } else {
            const float bj0 = bias[n], bj1 = bias[n + 1];
            *reinterpret_cast<float2*>(&C[(size_t)rowA * ldc + n]) =
                make_float2(c[j][0] + bj0, c[j][1] + bj1);
            *reinterpret_cast<float2*>(&C[(size_t)(rowA + 8) * ldc + n]) =
                make_float2(c[j][2] + bj0, c[j][3] + bj1);
        }
    }
}

// ---------------- depthwise conv ----------------
__global__ void __launch_bounds__(256) dwconv_k(const float* __restrict__ x,
                                                const float* __restrict__ dwk)
{
    const int s = blockIdx.x;
    const int b = blockIdx.y;
    for (int c = threadIdx.x; c < HIDC; c += 256) {
        float acc = 0.f;
#pragma unroll
        for (int tp = 0; tp < KW; tp++) {
            const int sp = s + tp - KW / 2;
            if (sp >= 0 && sp < SS)
                acc += x[((size_t)b * SS + sp) * HIDC + c] * dwk[c * KW + tp];
        }
        g_dw[((size_t)b * SS + s) * HIDC + c] = acc;
    }
}

// ---------------- tap softmax + windowed value conv ----------------
__global__ void __launch_bounds__(AHSZ) convout_k()
{
    const int m = blockIdx.x;
    const int b = m / SS;
    const int s = m % SS;
    __shared__ float filt[HK];
    const int t = threadIdx.x;

    if (t < NH) {
        float lg[KW];
        float mx = -1e30f;
#pragma unroll
        for (int i = 0; i < KW; i++) {
            lg[i] = g_logits[(size_t)m * HK + t * KW + i];
            mx = fmaxf(mx, lg[i]);
        }
        float sum = 0.f;
#pragma unroll
        for (int i = 0; i < KW; i++) { lg[i] = __expf(lg[i] - mx); sum += lg[i]; }
        const float is = 1.f / sum;
#pragma unroll
        for (int i = 0; i < KW; i++) filt[t * KW + i] = lg[i] * is;
    }
    __syncthreads();

    const int h = t / HD;
    float acc = 0.f;
#pragma unroll
    for (int tp = 0; tp < KW; tp++) {
        const int sp = s + tp - KW / 2;
        if (sp >= 0 && sp < SS)
            acc += g_v[((size_t)b * SS + sp) * AHSZ + t] * filt[h * KW + tp];
    }
    g_conv[(size_t)m * AHSZ + t] = acc;
}

// ---------------- launch ----------------
extern "C" void kernel_launch(void* const* d_in, const int* in_sizes, int n_in,
                              void* d_out, int out_size)
{
    const float* hidden = (const float*)d_in[0];
    const float* amask  = (const float*)d_in[1];
    const float* Wq = (const float*)d_in[2];  const float* bq = (const float*)d_in[3];
    const float* Wk = (const float*)d_in[4];  const float* bk = (const float*)d_in[5];
    const float* Wv = (const float*)d_in[6];  const float* bv = (const float*)d_in[7];
    const float* dwk = (const float*)d_in[8];
    const float* pw  = (const float*)d_in[9]; const float* sepb = (const float*)d_in[10];
    const float* Wak = (const float*)d_in[11]; const float* bak = (const float*)d_in[12];
    const float* Wsl = (const float*)d_in[13]; const float* bsl = (const float*)d_in[14];
    const float* Wcl = (const float*)d_in[15]; const float* bcl = (const float*)d_in[16];

    float *q, *k, *v, *dw, *ks, *cv, *lg, *attn_fb, *sco_fb;
    cudaGetSymbolAddress((void**)&q,   g_q);
    cudaGetSymbolAddress((void**)&k,   g_k);
    cudaGetSymbolAddress((void**)&v,   g_v);
    cudaGetSymbolAddress((void**)&dw,  g_dw);
    cudaGetSymbolAddress((void**)&ks,  g_ks);
    cudaGetSymbolAddress((void**)&cv,  g_conv);
    cudaGetSymbolAddress((void**)&lg,  g_logits);
    cudaGetSymbolAddress((void**)&attn_fb, g_attn_fb);
    cudaGetSymbolAddress((void**)&sco_fb,  g_sco_fb);

    float* outp = (float*)d_out;
    const size_t CTX_SZ = (size_t)MROWS * HIDC;
    const size_t ATT_OFF = CTX_SZ;
    const size_t ATT_SZ  = (size_t)MROWS * AHSZ;
    const size_t SCO_OFF = ATT_OFF + ATT_SZ;
    const size_t SCO_SZ  = (size_t)NZ * SS * SS;

    float* attnp = ((size_t)out_size >= ATT_OFF + ATT_SZ) ? outp + ATT_OFF : attn_fb;
    float* scop  = ((size_t)out_size >= SCO_OFF + SCO_SZ) ? outp + SCO_OFF : sco_fb;

    const dim3 blk(256);

    // 1) fused QKV projections (tf32 tensor)
    tgemm<T_QKV><<<dim3(AHSZ / 64, MROWS / 128, 3), blk>>>(
        hidden, nullptr, nullptr, Wq, Wk, Wv, bq, bk, bv, q, k, v,
        HIDC, HIDC, AHSZ, AHSZ);

    // 2) fused attention: scores + max-free softmax + fp16 PV
    {
        const int smem = FA_SMEM_F * (int)sizeof(float);
        cudaFuncSetAttribute(fattn_k, cudaFuncAttributeMaxDynamicSharedMemorySize, smem);
        fattn_k<<<dim3(SS / 128, NZ), 256, smem>>>(q, k, v, amask, scop, attnp);
    }

    // 3) depthwise conv
    dwconv_k<<<dim3(SS, BB), 256>>>(hidden, dwk);

    // 4) pointwise: ks_out = dw @ pw^T + sep_bias
    tgemm<T_NT><<<dim3(AHSZ / 64, MROWS / 128, 1), blk>>>(
        dw, nullptr, nullptr, pw, nullptr, nullptr, sepb, nullptr, nullptr,
        ks, nullptr, nullptr, HIDC, HIDC, HIDC, AHSZ);

    // 5) filter logits: (ks*q) @ Wak + bak
    tgemm<T_FILT><<<dim3(1, MROWS / 128, 1), blk>>>(
        ks, nullptr, q, Wak, nullptr, nullptr, bak, nullptr, nullptr,
        lg, nullptr, nullptr, AHSZ, AHSZ, HK, HK);

    // 6) tap softmax + windowed value conv
    convout_k<<<MROWS, AHSZ>>>();

    // 7) fused mix: context = [attn@Wsl+bsl | conv@Wcl+bcl]
    tgemm<T_MIX><<<dim3(AHSZ / 64, MROWS / 128, 2), blk>>>(
        attnp, cv, nullptr, Wsl, Wcl, nullptr, bsl, bcl, nullptr,
        outp, nullptr, nullptr, AHSZ, AHSZ, AHSZ, HIDC);
}

// round 7
// speedup vs baseline: 3.5934x; 1.4245x over previous
#include <cuda_runtime.h>
#include <cuda_fp16.h>
#include <math.h>
#include <stdint.h>

// ---------------- problem constants ----------------
#define BB    4
#define SS    2048
#define HIDC  768
#define NH    6
#define HD    64
#define AHSZ  384
#define KW    9
#define MROWS (BB*SS)      // 8192
#define NZ    (BB*NH)      // 24
#define HK    (NH*KW)      // 54

// ---------------- scratch ----------------
__device__ __half g_hidden_h[MROWS*HIDC];
__device__ __half g_qh[MROWS*AHSZ];
__device__ __half g_kh[MROWS*AHSZ];
__device__ __half g_vh[MROWS*AHSZ];
__device__ float  g_q [MROWS*AHSZ];      // fp32 q for FILT elementwise
__device__ float  g_v [MROWS*AHSZ];      // fp32 v for convout
__device__ __half g_dwh[MROWS*HIDC];
__device__ float  g_ks[MROWS*AHSZ];
__device__ __half g_convh[MROWS*AHSZ];
__device__ float  g_logits[MROWS*HK];
__device__ __half g_attn_h[MROWS*AHSZ];
// fp16 weight copies (prepped each call)
__device__ __half g_Wq_h[HIDC*AHSZ];
__device__ __half g_Wk_h[HIDC*AHSZ];
__device__ __half g_Wv_h[HIDC*AHSZ];
__device__ __half g_pwt_h[HIDC*AHSZ];    // pw transposed to [c][o]
__device__ __half g_Wsl_h[AHSZ*AHSZ];
__device__ __half g_Wcl_h[AHSZ*AHSZ];
__device__ __half g_Wak_h[AHSZ*64];      // padded 54 -> 64
// fallbacks
__device__ float g_attn_fb[MROWS*AHSZ];
__device__ float g_sco_fb [(size_t)NZ*SS*SS];

// ---------------- mma / ldmatrix helpers ----------------
__device__ __forceinline__ void mma_f16(float* d, const unsigned* a, unsigned b0, unsigned b1) {
    asm volatile(
        "mma.sync.aligned.m16n8k16.row.col.f32.f16.f16.f32 "
        "{%0,%1,%2,%3}, {%4,%5,%6,%7}, {%8,%9}, {%0,%1,%2,%3};"
        : "+f"(d[0]), "+f"(d[1]), "+f"(d[2]), "+f"(d[3])
        : "r"(a[0]), "r"(a[1]), "r"(a[2]), "r"(a[3]), "r"(b0), "r"(b1));
}
__device__ __forceinline__ unsigned pack_f16(float lo, float hi) {
    unsigned r;
    asm("cvt.rn.f16x2.f32 %0, %1, %2;" : "=r"(r) : "f"(hi), "f"(lo));
    return r;
}
__device__ __forceinline__ void ldsm4(unsigned* r, unsigned addr) {
    asm volatile("ldmatrix.sync.aligned.m8n8.x4.shared.b16 {%0,%1,%2,%3}, [%4];"
        : "=r"(r[0]), "=r"(r[1]), "=r"(r[2]), "=r"(r[3]) : "r"(addr));
}
__device__ __forceinline__ void ldsm4t(unsigned* r, unsigned addr) {
    asm volatile("ldmatrix.sync.aligned.m8n8.x4.trans.shared.b16 {%0,%1,%2,%3}, [%4];"
        : "=r"(r[0]), "=r"(r[1]), "=r"(r[2]), "=r"(r[3]) : "r"(addr));
}
__device__ __forceinline__ unsigned s2u(const void* p) {
    return (unsigned)__cvta_generic_to_shared(p);
}

// ---------------- prep kernels ----------------
__global__ void __launch_bounds__(256) cvt_h(const float4* __restrict__ s,
                                             __half2* __restrict__ d, int n4)
{
    const int i = blockIdx.x * 256 + threadIdx.x;
    if (i < n4) {
        const float4 x = s[i];
        d[2 * i + 0] = __floats2half2_rn(x.x, x.y);
        d[2 * i + 1] = __floats2half2_rn(x.z, x.w);
    }
}

__global__ void transpose_pw(const float* __restrict__ pw, __half* __restrict__ out)
{
    __shared__ float t[32][33];
    const int c0 = blockIdx.x * 32, o0 = blockIdx.y * 32;
    for (int i = threadIdx.y; i < 32; i += 8)
        t[i][threadIdx.x] = pw[(size_t)(o0 + i) * HIDC + c0 + threadIdx.x];
    __syncthreads();
    for (int i = threadIdx.y; i < 32; i += 8)
        out[(size_t)(c0 + i) * AHSZ + o0 + threadIdx.x] = __float2half(t[threadIdx.x][i]);
}

__global__ void pad_wak(const float* __restrict__ Wak, __half* __restrict__ out)
{
    const int r = blockIdx.x, t = threadIdx.x;  // 384 x 64
    out[r * 64 + t] = (t < HK) ? __float2half(Wak[r * HK + t]) : __half(0.f);
}

// =================== fp16 hgemm: 128x64x32 tile, ldmatrix frags ===================
enum { H_QKV = 0, H_NT = 1, H_FILT = 2, H_MIX = 3 };
#define A_P 40   // halves pitch of A tile (32+8)
#define B_P 72   // halves pitch of B tile (64+8)

template <int MODE>
__global__ void __launch_bounds__(256) hgemm(
    const __half* __restrict__ Ah0, const __half* __restrict__ Ah1,
    const float* __restrict__ Af0, const float* __restrict__ Af1,
    const __half* __restrict__ B0, const __half* __restrict__ B1, const __half* __restrict__ B2,
    const float* __restrict__ b0p, const float* __restrict__ b1p, const float* __restrict__ b2p,
    float* C0f, float* C1f, float* C2f,
    __half* C0h, __half* C1h, __half* C2h,
    int Kdim, int lda, int ldw, int ldc)
{
    __shared__ __half Ash[128 * A_P];
    __shared__ __half Bsh[32 * B_P];

    const int tid = threadIdx.x;
    const int w = tid >> 5, lane = tid & 31;
    const int lq = lane >> 2, lr = lane & 3;
    const int m0 = blockIdx.y * 128;
    const int n0 = blockIdx.x * 64;

    const __half* A = Ah0;
    const __half* B = B0;
    const float* bias = b0p;
    float* Cf = C0f;
    __half* Ch = C0h;
    if constexpr (MODE == H_QKV) {
        const int z = blockIdx.z;
        B    = (z == 0) ? B0 : ((z == 1) ? B1 : B2);
        bias = (z == 0) ? b0p : ((z == 1) ? b1p : b2p);
        Cf   = (z == 0) ? C0f : ((z == 1) ? C1f : C2f);   // may be null (k)
        Ch   = (z == 0) ? C0h : ((z == 1) ? C1h : C2h);
    }
    if constexpr (MODE == H_MIX) {
        const int z = blockIdx.z;
        A = z ? Ah1 : Ah0;
        B = z ? B1 : B0;
        bias = z ? b1p : b0p;
        Cf = C0f + z * AHSZ;
    }

    float c[8][4];
#pragma unroll
    for (int j = 0; j < 8; j++)
#pragma unroll
        for (int r = 0; r < 4; r++) c[j][r] = 0.f;

    // lane parts of ldmatrix addresses
    const unsigned a_lane = s2u(Ash) +
        (unsigned)(((w * 16 + (lane & 15)) * A_P + (lane >> 4) * 8) * 2);
    const unsigned b_lane = s2u(Bsh) +
        (unsigned)((((lane & 7) + ((lane >> 3) & 1) * 8) * B_P + ((lane >> 3) >> 1) * 8) * 2);

    const int ar = tid >> 1, acb = (tid & 1) * 16;
    const int br = tid >> 3, bcb = (tid & 7) * 8;

    for (int k0 = 0; k0 < Kdim; k0 += 32) {
        // ---- stage A ----
        if constexpr (MODE == H_FILT) {
            const float* pa = &Af0[(size_t)(m0 + ar) * lda + k0 + acb];
            const float* pb = &Af1[(size_t)(m0 + ar) * lda + k0 + acb];
            __half2* dst = reinterpret_cast<__half2*>(&Ash[ar * A_P + acb]);
#pragma unroll
            for (int u = 0; u < 4; u++) {
                const float4 xa = *reinterpret_cast<const float4*>(pa + u * 4);
                const float4 xb = *reinterpret_cast<const float4*>(pb + u * 4);
                dst[2 * u + 0] = __floats2half2_rn(xa.x * xb.x, xa.y * xb.y);
                dst[2 * u + 1] = __floats2half2_rn(xa.z * xb.z, xa.w * xb.w);
            }
        } else {
            const __half* ap = &A[(size_t)(m0 + ar) * lda + k0 + acb];
            *reinterpret_cast<uint4*>(&Ash[ar * A_P + acb]) =
                *reinterpret_cast<const uint4*>(ap);
            *reinterpret_cast<uint4*>(&Ash[ar * A_P + acb + 8]) =
                *reinterpret_cast<const uint4*>(ap + 8);
        }
        // ---- stage B ----
        *reinterpret_cast<uint4*>(&Bsh[br * B_P + bcb]) =
            *reinterpret_cast<const uint4*>(&B[(size_t)(k0 + br) * ldw + n0 + bcb]);
        __syncthreads();

        // ---- compute ----
#pragma unroll
        for (int kc = 0; kc < 2; kc++) {
            unsigned af[4];
            ldsm4(af, a_lane + (unsigned)(kc * 32));        // 16 halves = 32B
#pragma unroll
            for (int nb = 0; nb < 4; nb++) {
                unsigned kb[4];
                ldsm4t(kb, b_lane + (unsigned)((kc * 16 * B_P + nb * 16) * 2));
                mma_f16(c[2 * nb],     af, kb[0], kb[1]);
                mma_f16(c[2 * nb + 1], af, kb[2], kb[3]);
            }
        }
        __syncthreads();
    }

    // ---- epilogue ----
    const int rowA = m0 + w * 16 + lq;
#pragma unroll
    for (int j = 0; j < 8; j++) {
        const int n = n0 + j * 8 + 2 * lr;
        if constexpr (MODE == H_FILT) {
            if (n < HK) {
                const float bj0 = bias[n], bj1 = bias[n + 1];
                *reinterpret_cast<float2*>(&C0f[(size_t)rowA * HK + n]) =
                    make_float2(c[j][0] + bj0, c[j][1] + bj1);
                *reinterpret_cast<float2*>(&C0f[(size_t)(rowA + 8) * HK + n]) =
                    make_float2(c[j][2] + bj0, c[j][3] + bj1);
            }
        } else {
            const float bj0 = bias[n], bj1 = bias[n + 1];
            const float v0 = c[j][0] + bj0, v1 = c[j][1] + bj1;
            const float v2 = c[j][2] + bj0, v3 = c[j][3] + bj1;
            if (Cf) {
                *reinterpret_cast<float2*>(&Cf[(size_t)rowA * ldc + n]) = make_float2(v0, v1);
                *reinterpret_cast<float2*>(&Cf[(size_t)(rowA + 8) * ldc + n]) = make_float2(v2, v3);
            }
            if constexpr (MODE == H_QKV) {
                *reinterpret_cast<unsigned*>(&Ch[(size_t)rowA * ldc + n]) = pack_f16(v0, v1);
                *reinterpret_cast<unsigned*>(&Ch[(size_t)(rowA + 8) * ldc + n]) = pack_f16(v2, v3);
            }
        }
    }
}

// =================== fused flash attention v3 (all fp16 mma) ===================
// 128 q-rows/CTA, 8 warps (warp w: rows w*16..+15, all 64 keys per kt).
// Q frags register-resident via ldmatrix. S = QK^T fp16 mma (K non-trans ldsm).
// P = exp(S) repacked in registers; PV fp16 with trans-ldsm V frags.
#define FQ_P 72
#define FA_SMEM_B (128*FQ_P*2 + SS*4)   // Q region (reused by K+V) + mask

__global__ void __launch_bounds__(256, 2) fattn_k(
    const __half* __restrict__ qh, const __half* __restrict__ kh, const __half* __restrict__ vh,
    const float* __restrict__ amask, float* __restrict__ scores,
    float* __restrict__ attn, __half* __restrict__ attnh)
{
    extern __shared__ char smc[];
    __half* Qh = (__half*)smc;               // [128][72]
    __half* Kh = (__half*)smc;               // [64][72] overlays Q
    __half* Vh = (__half*)(smc + 64 * FQ_P * 2);
    float* msk = (float*)(smc + 128 * FQ_P * 2);

    const int tid  = threadIdx.x;
    const int w    = tid >> 5, lane = tid & 31;
    const int lq   = lane >> 2, lr = lane & 3;
    const int m0   = blockIdx.x * 128;
    const int z    = blockIdx.y, b = z / NH, h = z % NH;
    const int row0 = w * 16 + lq;

    // mask into smem
    {
        const float4* s4 = reinterpret_cast<const float4*>(amask + (size_t)b * SS);
        float4* d4 = reinterpret_cast<float4*>(msk);
        for (int i = tid; i < SS / 4; i += 256) d4[i] = s4[i];
    }
    // stage Q
    {
        const int r = tid >> 1, cb = (tid & 1) * 32;
        const __half* qp = qh + ((size_t)(b * SS + m0 + r)) * AHSZ + h * HD + cb;
        uint4* dst = reinterpret_cast<uint4*>(&Qh[r * FQ_P + cb]);
#pragma unroll
        for (int u = 0; u < 4; u++) dst[u] = *reinterpret_cast<const uint4*>(qp + u * 8);
    }
    __syncthreads();

    // lift Q frags
    unsigned Qa[4][4];
    {
        const unsigned q_lane = s2u(Qh) +
            (unsigned)(((w * 16 + (lane & 15)) * FQ_P + (lane >> 4) * 8) * 2);
#pragma unroll
        for (int kc = 0; kc < 4; kc++) ldsm4(Qa[kc], q_lane + (unsigned)(kc * 32));
    }
    __syncthreads();   // Q region about to be overwritten

    float o[8][4];
#pragma unroll
    for (int d = 0; d < 8; d++)
#pragma unroll
        for (int r = 0; r < 4; r++) o[d][r] = 0.f;
    float lacc0 = 0.f, lacc1 = 0.f;

    const __half* kbase = kh + (size_t)b * SS * AHSZ + h * HD;
    const __half* vbase = vh + (size_t)b * SS * AHSZ + h * HD;
    float* sco = scores + (size_t)z * SS * SS;

    const unsigned k_lane = s2u(Kh) +
        (unsigned)((((lane & 15)) * FQ_P + (lane >> 4) * 8) * 2);
    const unsigned v_lane = s2u(Vh) +
        (unsigned)((((lane & 7) + ((lane >> 3) & 1) * 8) * FQ_P + ((lane >> 3) >> 1) * 8) * 2);

    for (int kt = 0; kt < 32; kt++) {
        const int n0 = kt * 64;
        // ---- stage K, V tiles ----
        {
            const int r = tid >> 2, cb = (tid & 3) * 16;
            const __half* kp = kbase + (size_t)(n0 + r) * AHSZ + cb;
            const __half* vp = vbase + (size_t)(n0 + r) * AHSZ + cb;
            uint4* kd = reinterpret_cast<uint4*>(&Kh[r * FQ_P + cb]);
            uint4* vd = reinterpret_cast<uint4*>(&Vh[r * FQ_P + cb]);
            kd[0] = *reinterpret_cast<const uint4*>(kp);
            kd[1] = *reinterpret_cast<const uint4*>(kp + 8);
            vd[0] = *reinterpret_cast<const uint4*>(vp);
            vd[1] = *reinterpret_cast<const uint4*>(vp + 8);
        }
        __syncthreads();

#pragma unroll
        for (int kg = 0; kg < 4; kg++) {       // 16-key groups
            // ---- S = Q K^T ----
            float c[2][4];
#pragma unroll
            for (int jj = 0; jj < 2; jj++)
#pragma unroll
                for (int r = 0; r < 4; r++) c[jj][r] = 0.f;
#pragma unroll
            for (int kc = 0; kc < 4; kc++) {
                unsigned kb[4];
                ldsm4(kb, k_lane + (unsigned)((kg * 16 * FQ_P + kc * 16) * 2));
                mma_f16(c[0], Qa[kc], kb[0], kb[2]);   // keys kg*16..+7
                mma_f16(c[1], Qa[kc], kb[1], kb[3]);   // keys kg*16+8..+15
            }

            // ---- epilogue: scale+mask, store scores, exp, repack ----
            unsigned pa[4];
#pragma unroll
            for (int jj = 0; jj < 2; jj++) {
                const int colL = kg * 16 + jj * 8 + 2 * lr;
                const float mk0 = msk[n0 + colL], mk1 = msk[n0 + colL + 1];
                const float s0 = c[jj][0] * 0.125f + mk0;
                const float s1 = c[jj][1] * 0.125f + mk1;
                const float s2 = c[jj][2] * 0.125f + mk0;
                const float s3 = c[jj][3] * 0.125f + mk1;
                *reinterpret_cast<float2*>(&sco[(size_t)(m0 + row0) * SS + n0 + colL]) =
                    make_float2(s0, s1);
                *reinterpret_cast<float2*>(&sco[(size_t)(m0 + row0 + 8) * SS + n0 + colL]) =
                    make_float2(s2, s3);
                const float p0 = __expf(s0), p1 = __expf(s1);
                const float p2 = __expf(s2), p3 = __expf(s3);
                lacc0 += p0 + p1;
                lacc1 += p2 + p3;
                pa[jj * 2 + 0] = pack_f16(p0, p1);
                pa[jj * 2 + 1] = pack_f16(p2, p3);
            }

            // ---- PV over these 16 keys ----
#pragma unroll
            for (int dp = 0; dp < 4; dp++) {
                unsigned vb[4];
                ldsm4t(vb, v_lane + (unsigned)((kg * 16 * FQ_P + dp * 16) * 2));
                mma_f16(o[2 * dp],     pa, vb[0], vb[1]);
                mma_f16(o[2 * dp + 1], pa, vb[2], vb[3]);
            }
        }
        __syncthreads();
    }

    // ---- normalize & write attn (fp32 + fp16) ----
    float l0 = lacc0, l1 = lacc1;
    l0 += __shfl_xor_sync(0xFFFFFFFFu, l0, 1);
    l0 += __shfl_xor_sync(0xFFFFFFFFu, l0, 2);
    l1 += __shfl_xor_sync(0xFFFFFFFFu, l1, 1);
    l1 += __shfl_xor_sync(0xFFFFFFFFu, l1, 2);
    const float inv0 = 1.f / l0, inv1 = 1.f / l1;

#pragma unroll
    for (int d = 0; d < 8; d++) {
        const int col = h * HD + d * 8 + 2 * lr;
        const size_t r0 = ((size_t)(b * SS + m0 + row0)) * AHSZ + col;
        const size_t r1 = ((size_t)(b * SS + m0 + row0 + 8)) * AHSZ + col;
        const float v0 = o[d][0] * inv0, v1 = o[d][1] * inv0;
        const float v2 = o[d][2] * inv1, v3 = o[d][3] * inv1;
        *reinterpret_cast<float2*>(&attn[r0]) = make_float2(v0, v1);
        *reinterpret_cast<float2*>(&attn[r1]) = make_float2(v2, v3);
        *reinterpret_cast<unsigned*>(&attnh[r0]) = pack_f16(v0, v1);
        *reinterpret_cast<unsigned*>(&attnh[r1]) = pack_f16(v2, v3);
    }
}

// ---------------- depthwise conv (fp32 in, fp16 out) ----------------
__global__ void __launch_bounds__(384) dwconv_k(const float* __restrict__ x,
                                                const float* __restrict__ dwk)
{
    const int s = blockIdx.x;
    const int b = blockIdx.y;
    const int c0 = threadIdx.x * 2;
    float a0 = 0.f, a1 = 0.f;
#pragma unroll
    for (int tp = 0; tp < KW; tp++) {
        const int sp = s + tp - KW / 2;
        if (sp >= 0 && sp < SS) {
            const float2 xv = *reinterpret_cast<const float2*>(
                &x[((size_t)b * SS + sp) * HIDC + c0]);
            a0 += xv.x * dwk[c0 * KW + tp];
            a1 += xv.y * dwk[(c0 + 1) * KW + tp];
        }
    }
    *reinterpret_cast<__half2*>(&g_dwh[((size_t)b * SS + s) * HIDC + c0]) =
        __floats2half2_rn(a0, a1);
}

// ---------------- tap softmax + windowed value conv (fp16 out) ----------------
__global__ void __launch_bounds__(AHSZ) convout_k()
{
    const int m = blockIdx.x;
    const int b = m / SS;
    const int s = m % SS;
    __shared__ float filt[HK];
    const int t = threadIdx.x;

    if (t < NH) {
        float lg[KW];
        float mx = -1e30f;
#pragma unroll
        for (int i = 0; i < KW; i++) {
            lg[i] = g_logits[(size_t)m * HK + t * KW + i];
            mx = fmaxf(mx, lg[i]);
        }
        float sum = 0.f;
#pragma unroll
        for (int i = 0; i < KW; i++) { lg[i] = __expf(lg[i] - mx); sum += lg[i]; }
        const float is = 1.f / sum;
#pragma unroll
        for (int i = 0; i < KW; i++) filt[t * KW + i] = lg[i] * is;
    }
    __syncthreads();

    const int h = t / HD;
    float acc = 0.f;
#pragma unroll
    for (int tp = 0; tp < KW; tp++) {
        const int sp = s + tp - KW / 2;
        if (sp >= 0 && sp < SS)
            acc += g_v[((size_t)b * SS + sp) * AHSZ + t] * filt[h * KW + tp];
    }
    g_convh[(size_t)m * AHSZ + t] = __float2half(acc);
}

// ---------------- launch ----------------
extern "C" void kernel_launch(void* const* d_in, const int* in_sizes, int n_in,
                              void* d_out, int out_size)
{
    const float* hidden = (const float*)d_in[0];
    const float* amask  = (const float*)d_in[1];
    const float* Wq = (const float*)d_in[2];  const float* bq = (const float*)d_in[3];
    const float* Wk = (const float*)d_in[4];  const float* bk = (const float*)d_in[5];
    const float* Wv = (const float*)d_in[6];  const float* bv = (const float*)d_in[7];
    const float* dwk = (const float*)d_in[8];
    const float* pw  = (const float*)d_in[9]; const float* sepb = (const float*)d_in[10];
    const float* Wak = (const float*)d_in[11]; const float* bak = (const float*)d_in[12];
    const float* Wsl = (const float*)d_in[13]; const float* bsl = (const float*)d_in[14];
    const float* Wcl = (const float*)d_in[15]; const float* bcl = (const float*)d_in[16];

    __half *hidh, *qhp, *khp, *vhp, *dwh, *convh, *attnh;
    __half *wqh, *wkh, *wvh, *pwth, *wslh, *wclh, *wakh;
    float *qf, *vf, *ks, *lg, *attn_fb, *sco_fb;
    cudaGetSymbolAddress((void**)&hidh,  g_hidden_h);
    cudaGetSymbolAddress((void**)&qhp,   g_qh);
    cudaGetSymbolAddress((void**)&khp,   g_kh);
    cudaGetSymbolAddress((void**)&vhp,   g_vh);
    cudaGetSymbolAddress((void**)&qf,    g_q);
    cudaGetSymbolAddress((void**)&vf,    g_v);
    cudaGetSymbolAddress((void**)&dwh,   g_dwh);
    cudaGetSymbolAddress((void**)&ks,    g_ks);
    cudaGetSymbolAddress((void**)&convh, g_convh);
    cudaGetSymbolAddress((void**)&lg,    g_logits);
    cudaGetSymbolAddress((void**)&attnh, g_attn_h);
    cudaGetSymbolAddress((void**)&wqh,   g_Wq_h);
    cudaGetSymbolAddress((void**)&wkh,   g_Wk_h);
    cudaGetSymbolAddress((void**)&wvh,   g_Wv_h);
    cudaGetSymbolAddress((void**)&pwth,  g_pwt_h);
    cudaGetSymbolAddress((void**)&wslh,  g_Wsl_h);
    cudaGetSymbolAddress((void**)&wclh,  g_Wcl_h);
    cudaGetSymbolAddress((void**)&wakh,  g_Wak_h);
    cudaGetSymbolAddress((void**)&attn_fb, g_attn_fb);
    cudaGetSymbolAddress((void**)&sco_fb,  g_sco_fb);

    float* outp = (float*)d_out;
    const size_t CTX_SZ = (size_t)MROWS * HIDC;
    const size_t ATT_OFF = CTX_SZ;
    const size_t ATT_SZ  = (size_t)MROWS * AHSZ;
    const size_t SCO_OFF = ATT_OFF + ATT_SZ;
    const size_t SCO_SZ  = (size_t)NZ * SS * SS;
    float* attnp = ((size_t)out_size >= ATT_OFF + ATT_SZ) ? outp + ATT_OFF : attn_fb;
    float* scop  = ((size_t)out_size >= SCO_OFF + SCO_SZ) ? outp + SCO_OFF : sco_fb;

    // ---- prep: fp16 conversions ----
    cvt_h<<<(MROWS * HIDC / 4 + 255) / 256, 256>>>((const float4*)hidden, (__half2*)hidh, MROWS * HIDC / 4);
    cvt_h<<<(HIDC * AHSZ / 4 + 255) / 256, 256>>>((const float4*)Wq, (__half2*)wqh, HIDC * AHSZ / 4);
    cvt_h<<<(HIDC * AHSZ / 4 + 255) / 256, 256>>>((const float4*)Wk, (__half2*)wkh, HIDC * AHSZ / 4);
    cvt_h<<<(HIDC * AHSZ / 4 + 255) / 256, 256>>>((const float4*)Wv, (__half2*)wvh, HIDC * AHSZ / 4);
    cvt_h<<<(AHSZ * AHSZ / 4 + 255) / 256, 256>>>((const float4*)Wsl, (__half2*)wslh, AHSZ * AHSZ / 4);
    cvt_h<<<(AHSZ * AHSZ / 4 + 255) / 256, 256>>>((const float4*)Wcl, (__half2*)wclh, AHSZ * AHSZ / 4);
    transpose_pw<<<dim3(HIDC / 32, AHSZ / 32), dim3(32, 8)>>>(pw, pwth);
    pad_wak<<<AHSZ, 64>>>(Wak, wakh);

    const dim3 blk(256);

    // 1) fused QKV (fp16): q -> fp32+fp16, k -> fp16, v -> fp32+fp16
    hgemm<H_QKV><<<dim3(AHSZ / 64, MROWS / 128, 3), blk>>>(
        hidh, nullptr, nullptr, nullptr,
        wqh, wkh, wvh, bq, bk, bv,
        qf, nullptr, vf, qhp, khp, vhp,
        HIDC, HIDC, AHSZ, AHSZ);

    // 2) fused attention (all fp16 mma): scores + max-free softmax + PV
    {
        cudaFuncSetAttribute(fattn_k, cudaFuncAttributeMaxDynamicSharedMemorySize, FA_SMEM_B);
        fattn_k<<<dim3(SS / 128, NZ), 256, FA_SMEM_B>>>(qhp, khp, vhp, amask, scop, attnp, attnh);
    }

    // 3) depthwise conv -> fp16
    dwconv_k<<<dim3(SS, BB), 384>>>(hidden, dwk);

    // 4) pointwise: ks = dw @ pw^T + sep_bias (fp32 out)
    hgemm<H_NT><<<dim3(AHSZ / 64, MROWS / 128, 1), blk>>>(
        dwh, nullptr, nullptr, nullptr,
        pwth, nullptr, nullptr, sepb, nullptr, nullptr,
        ks, nullptr, nullptr, nullptr, nullptr, nullptr,
        HIDC, HIDC, AHSZ, AHSZ);

    // 5) filter logits: (ks*q) @ Wak + bak
    hgemm<H_FILT><<<dim3(1, MROWS / 128, 1), blk>>>(
        nullptr, nullptr, ks, qf,
        wakh, nullptr, nullptr, bak, nullptr, nullptr,
        lg, nullptr, nullptr, nullptr, nullptr, nullptr,
        AHSZ, AHSZ, 64, HK);

    // 6) tap softmax + windowed value conv -> fp16
    convout_k<<<MROWS, AHSZ>>>();

    // 7) fused mix: context = [attn@Wsl+bsl | conv@Wcl+bcl]
    hgemm<H_MIX><<<dim3(AHSZ / 64, MROWS / 128, 2), blk>>>(
        attnh, convh, nullptr, nullptr,
        wslh, wclh, nullptr, bsl, bcl, nullptr,
        outp, nullptr, nullptr, nullptr, nullptr, nullptr,
        AHSZ, AHSZ, AHSZ, HIDC);
}

// round 8
// speedup vs baseline: 4.4207x; 1.2302x over previous
#include <cuda_runtime.h>
#include <cuda_fp16.h>
#include <math.h>
#include <stdint.h>

// ---------------- problem constants ----------------
#define BB    4
#define SS    2048
#define HIDC  768
#define NH    6
#define HD    64
#define AHSZ  384
#define KW    9
#define MROWS (BB*SS)      // 8192
#define NZ    (BB*NH)      // 24
#define HK    (NH*KW)      // 54

// ---------------- scratch ----------------
__device__ __half g_hidden_h[MROWS*HIDC];
__device__ __half g_qh[MROWS*AHSZ];
__device__ __half g_kh[MROWS*AHSZ];
__device__ __half g_vh[MROWS*AHSZ];
__device__ float  g_q [MROWS*AHSZ];      // fp32 q for FILT elementwise
__device__ float  g_v [MROWS*AHSZ];      // fp32 v for convout
__device__ __half g_dwh[MROWS*HIDC];
__device__ float  g_ks[MROWS*AHSZ];
__device__ __half g_convh[MROWS*AHSZ];
__device__ float  g_logits[MROWS*HK];
__device__ __half g_attn_h[MROWS*AHSZ];
// fp16 weight copies
__device__ __half g_Wq_h[HIDC*AHSZ];
__device__ __half g_Wk_h[HIDC*AHSZ];
__device__ __half g_Wv_h[HIDC*AHSZ];
__device__ __half g_pwt_h[HIDC*AHSZ];    // pw transposed to [c][o]
__device__ __half g_Wsl_h[AHSZ*AHSZ];
__device__ __half g_Wcl_h[AHSZ*AHSZ];
__device__ __half g_Wak_h[AHSZ*64];      // padded 54 -> 64
// fallbacks
__device__ float g_attn_fb[MROWS*AHSZ];
__device__ float g_sco_fb [(size_t)NZ*SS*SS];

// ---------------- mma / ldmatrix / cp.async helpers ----------------
__device__ __forceinline__ void mma_f16(float* d, const unsigned* a, unsigned b0, unsigned b1) {
    asm volatile(
        "mma.sync.aligned.m16n8k16.row.col.f32.f16.f16.f32 "
        "{%0,%1,%2,%3}, {%4,%5,%6,%7}, {%8,%9}, {%0,%1,%2,%3};"
        : "+f"(d[0]), "+f"(d[1]), "+f"(d[2]), "+f"(d[3])
        : "r"(a[0]), "r"(a[1]), "r"(a[2]), "r"(a[3]), "r"(b0), "r"(b1));
}
__device__ __forceinline__ unsigned pack_f16(float lo, float hi) {
    unsigned r;
    asm("cvt.rn.f16x2.f32 %0, %1, %2;" : "=r"(r) : "f"(hi), "f"(lo));
    return r;
}
__device__ __forceinline__ void ldsm4(unsigned* r, unsigned addr) {
    asm volatile("ldmatrix.sync.aligned.m8n8.x4.shared.b16 {%0,%1,%2,%3}, [%4];"
        : "=r"(r[0]), "=r"(r[1]), "=r"(r[2]), "=r"(r[3]) : "r"(addr));
}
__device__ __forceinline__ void ldsm4t(unsigned* r, unsigned addr) {
    asm volatile("ldmatrix.sync.aligned.m8n8.x4.trans.shared.b16 {%0,%1,%2,%3}, [%4];"
        : "=r"(r[0]), "=r"(r[1]), "=r"(r[2]), "=r"(r[3]) : "r"(addr));
}
__device__ __forceinline__ unsigned s2u(const void* p) {
    return (unsigned)__cvta_generic_to_shared(p);
}
__device__ __forceinline__ void cpa16(unsigned dst, const void* src) {
    asm volatile("cp.async.ca.shared.global [%0], [%1], 16;" :: "r"(dst), "l"(src));
}
__device__ __forceinline__ void cpa_commit() { asm volatile("cp.async.commit_group;"); }
template <int N>
__device__ __forceinline__ void cpa_wait() { asm volatile("cp.async.wait_group %0;" :: "n"(N)); }

// ---------------- prep kernels ----------------
__global__ void __launch_bounds__(256) cvt_h(const float4* __restrict__ s,
                                             __half2* __restrict__ d, int n4)
{
    const int i = blockIdx.x * 256 + threadIdx.x;
    if (i < n4) {
        const float4 x = s[i];
        d[2 * i + 0] = __floats2half2_rn(x.x, x.y);
        d[2 * i + 1] = __floats2half2_rn(x.z, x.w);
    }
}

__global__ void transpose_pw(const float* __restrict__ pw, __half* __restrict__ out)
{
    __shared__ float t[32][33];
    const int c0 = blockIdx.x * 32, o0 = blockIdx.y * 32;
    for (int i = threadIdx.y; i < 32; i += 8)
        t[i][threadIdx.x] = pw[(size_t)(o0 + i) * HIDC + c0 + threadIdx.x];
    __syncthreads();
    for (int i = threadIdx.y; i < 32; i += 8)
        out[(size_t)(c0 + i) * AHSZ + o0 + threadIdx.x] = __float2half(t[threadIdx.x][i]);
}

__global__ void pad_wak(const float* __restrict__ Wak, __half* __restrict__ out)
{
    const int r = blockIdx.x, t = threadIdx.x;  // 384 x 64
    out[r * 64 + t] = (t < HK) ? __float2half(Wak[r * HK + t]) : __half(0.f);
}

// =================== fp16 hgemm (double-buffered cp.async): 128x64x32 ===================
enum { H_QKV = 0, H_NT = 1, H_MIX = 3 };
#define A_P 40   // halves pitch of A tile (32+8); 80B row stride (16B multiple)
#define B_P 72   // halves pitch of B tile (64+8); 144B row stride

template <int MODE>
__global__ void __launch_bounds__(256) hgemm(
    const __half* __restrict__ Ah0, const __half* __restrict__ Ah1,
    const __half* __restrict__ B0, const __half* __restrict__ B1, const __half* __restrict__ B2,
    const float* __restrict__ b0p, const float* __restrict__ b1p, const float* __restrict__ b2p,
    float* C0f, float* C1f, float* C2f,
    __half* C0h, __half* C1h, __half* C2h,
    int Kdim, int lda, int ldw, int ldc)
{
    __shared__ __half Ash[2][128 * A_P];
    __shared__ __half Bsh[2][32 * B_P];

    const int tid = threadIdx.x;
    const int w = tid >> 5, lane = tid & 31;
    const int lq = lane >> 2, lr = lane & 3;
    const int m0 = blockIdx.y * 128;
    const int n0 = blockIdx.x * 64;

    const __half* A = Ah0;
    const __half* B = B0;
    const float* bias = b0p;
    float* Cf = C0f;
    __half* Ch = C0h;
    if constexpr (MODE == H_QKV) {
        const int z = blockIdx.z;
        B    = (z == 0) ? B0 : ((z == 1) ? B1 : B2);
        bias = (z == 0) ? b0p : ((z == 1) ? b1p : b2p);
        Cf   = (z == 0) ? C0f : ((z == 1) ? C1f : C2f);
        Ch   = (z == 0) ? C0h : ((z == 1) ? C1h : C2h);
    }
    if constexpr (MODE == H_MIX) {
        const int z = blockIdx.z;
        A = z ? Ah1 : Ah0;
        B = z ? B1 : B0;
        bias = z ? b1p : b0p;
        Cf = C0f + z * AHSZ;
    }

    float c[8][4];
#pragma unroll
    for (int j = 0; j < 8; j++)
#pragma unroll
        for (int r = 0; r < 4; r++) c[j][r] = 0.f;

    const unsigned a_lane_b = s2u(Ash) +
        (unsigned)(((w * 16 + (lane & 15)) * A_P + (lane >> 4) * 8) * 2);
    const unsigned b_lane_b = s2u(Bsh) +
        (unsigned)((((lane & 7) + ((lane >> 3) & 1) * 8) * B_P + ((lane >> 3) >> 1) * 8) * 2);

    const int ar = tid >> 1, acb = (tid & 1) * 16;
    const int br = tid >> 3, bcb = (tid & 7) * 8;

    const unsigned a_st = s2u(Ash) + (unsigned)((ar * A_P + acb) * 2);
    const unsigned b_st = s2u(Bsh) + (unsigned)((br * B_P + bcb) * 2);
    const unsigned A_STAGE = 128 * A_P * 2;
    const unsigned B_STAGE = 32 * B_P * 2;

    const int NIT = Kdim / 32;
    // prologue: stage 0
    {
        const __half* ap = &A[(size_t)(m0 + ar) * lda + acb];
        cpa16(a_st, ap);
        cpa16(a_st + 16, ap + 8);
        cpa16(b_st, &B[(size_t)br * ldw + n0 + bcb]);
        cpa_commit();
    }

    for (int it = 0; it < NIT; it++) {
        if (it + 1 < NIT) {
            const int k0 = (it + 1) * 32;
            const unsigned s = (unsigned)((it + 1) & 1);
            const __half* ap = &A[(size_t)(m0 + ar) * lda + k0 + acb];
            cpa16(a_st + s * A_STAGE, ap);
            cpa16(a_st + s * A_STAGE + 16, ap + 8);
            cpa16(b_st + s * B_STAGE, &B[(size_t)(k0 + br) * ldw + n0 + bcb]);
            cpa_commit();
            cpa_wait<1>();
        } else {
            cpa_wait<0>();
        }
        __syncthreads();

        const unsigned s = (unsigned)(it & 1);
        const unsigned a_lane = a_lane_b + s * A_STAGE;
        const unsigned b_lane = b_lane_b + s * B_STAGE;
#pragma unroll
        for (int kc = 0; kc < 2; kc++) {
            unsigned af[4];
            ldsm4(af, a_lane + (unsigned)(kc * 32));
#pragma unroll
            for (int nb = 0; nb < 4; nb++) {
                unsigned kb[4];
                ldsm4t(kb, b_lane + (unsigned)((kc * 16 * B_P + nb * 16) * 2));
                mma_f16(c[2 * nb],     af, kb[0], kb[1]);
                mma_f16(c[2 * nb + 1], af, kb[2], kb[3]);
            }
        }
        __syncthreads();
    }

    // ---- epilogue ----
    const int rowA = m0 + w * 16 + lq;
#pragma unroll
    for (int j = 0; j < 8; j++) {
        const int n = n0 + j * 8 + 2 * lr;
        const float bj0 = bias[n], bj1 = bias[n + 1];
        const float v0 = c[j][0] + bj0, v1 = c[j][1] + bj1;
        const float v2 = c[j][2] + bj0, v3 = c[j][3] + bj1;
        if (Cf) {
            *reinterpret_cast<float2*>(&Cf[(size_t)rowA * ldc + n]) = make_float2(v0, v1);
            *reinterpret_cast<float2*>(&Cf[(size_t)(rowA + 8) * ldc + n]) = make_float2(v2, v3);
        }
        if constexpr (MODE == H_QKV) {
            *reinterpret_cast<unsigned*>(&Ch[(size_t)rowA * ldc + n]) = pack_f16(v0, v1);
            *reinterpret_cast<unsigned*>(&Ch[(size_t)(rowA + 8) * ldc + n]) = pack_f16(v2, v3);
        }
    }
}

// =================== FILT: (ks*q) @ Wak + bak (single-buffer, fp32 A-stage) ===================
__global__ void __launch_bounds__(256) hgemm_filt(
    const float* __restrict__ Af0, const float* __restrict__ Af1,
    const __half* __restrict__ B0, const float* __restrict__ bias, float* __restrict__ Cf)
{
    __shared__ __half Ash[128 * A_P];
    __shared__ __half Bsh[32 * B_P];

    const int tid = threadIdx.x;
    const int w = tid >> 5, lane = tid & 31;
    const int lq = lane >> 2, lr = lane & 3;
    const int m0 = blockIdx.y * 128;

    float c[8][4];
#pragma unroll
    for (int j = 0; j < 8; j++)
#pragma unroll
        for (int r = 0; r < 4; r++) c[j][r] = 0.f;

    const unsigned a_lane = s2u(Ash) +
        (unsigned)(((w * 16 + (lane & 15)) * A_P + (lane >> 4) * 8) * 2);
    const unsigned b_lane = s2u(Bsh) +
        (unsigned)((((lane & 7) + ((lane >> 3) & 1) * 8) * B_P + ((lane >> 3) >> 1) * 8) * 2);

    const int ar = tid >> 1, acb = (tid & 1) * 16;
    const int br = tid >> 3, bcb = (tid & 7) * 8;

    for (int k0 = 0; k0 < AHSZ; k0 += 32) {
        {
            const float* pa = &Af0[(size_t)(m0 + ar) * AHSZ + k0 + acb];
            const float* pb = &Af1[(size_t)(m0 + ar) * AHSZ + k0 + acb];
            __half2* dst = reinterpret_cast<__half2*>(&Ash[ar * A_P + acb]);
#pragma unroll
            for (int u = 0; u < 4; u++) {
                const float4 xa = *reinterpret_cast<const float4*>(pa + u * 4);
                const float4 xb = *reinterpret_cast<const float4*>(pb + u * 4);
                dst[2 * u + 0] = __floats2half2_rn(xa.x * xb.x, xa.y * xb.y);
                dst[2 * u + 1] = __floats2half2_rn(xa.z * xb.z, xa.w * xb.w);
            }
        }
        *reinterpret_cast<uint4*>(&Bsh[br * B_P + bcb]) =
            *reinterpret_cast<const uint4*>(&B0[(size_t)(k0 + br) * 64 + bcb]);
        __syncthreads();

#pragma unroll
        for (int kc = 0; kc < 2; kc++) {
            unsigned af[4];
            ldsm4(af, a_lane + (unsigned)(kc * 32));
#pragma unroll
            for (int nb = 0; nb < 4; nb++) {
                unsigned kb[4];
                ldsm4t(kb, b_lane + (unsigned)((kc * 16 * B_P + nb * 16) * 2));
                mma_f16(c[2 * nb],     af, kb[0], kb[1]);
                mma_f16(c[2 * nb + 1], af, kb[2], kb[3]);
            }
        }
        __syncthreads();
    }

    const int rowA = m0 + w * 16 + lq;
#pragma unroll
    for (int j = 0; j < 8; j++) {
        const int n = j * 8 + 2 * lr;
        if (n < HK) {
            const float bj0 = bias[n], bj1 = bias[n + 1];
            *reinterpret_cast<float2*>(&Cf[(size_t)rowA * HK + n]) =
                make_float2(c[j][0] + bj0, c[j][1] + bj1);
            *reinterpret_cast<float2*>(&Cf[(size_t)(rowA + 8) * HK + n]) =
                make_float2(c[j][2] + bj0, c[j][3] + bj1);
        }
    }
}

// =================== fused flash attention (fp16, cp.async double-buffered K/V) ===================
#define FQ_P 72
#define KV_STAGE (64*FQ_P*2)                    // bytes per K (or V) stage
#define FA_SMEM_B (4*KV_STAGE/2*2 + SS*4)       // 2*(K+V) stages + mask = 36864 + 8192

__global__ void __launch_bounds__(256, 2) fattn_k(
    const __half* __restrict__ qh, const __half* __restrict__ kh, const __half* __restrict__ vh,
    const float* __restrict__ amask, float* __restrict__ scores,
    float* __restrict__ attn, __half* __restrict__ attnh)
{
    extern __shared__ char smc[];
    __half* Qh = (__half*)smc;                        // [128][72] staging (reuses K stages)
    __half* Ksh = (__half*)smc;                       // [2][64][72]
    __half* Vsh = (__half*)(smc + 2 * KV_STAGE);      // [2][64][72]
    float* msk = (float*)(smc + 4 * KV_STAGE);

    const int tid  = threadIdx.x;
    const int w    = tid >> 5, lane = tid & 31;
    const int lq   = lane >> 2, lr = lane & 3;
    const int m0   = blockIdx.x * 128;
    const int z    = blockIdx.y, b = z / NH, h = z % NH;
    const int row0 = w * 16 + lq;

    // mask into smem
    {
        const float4* s4 = reinterpret_cast<const float4*>(amask + (size_t)b * SS);
        float4* d4 = reinterpret_cast<float4*>(msk);
        for (int i = tid; i < SS / 4; i += 256) d4[i] = s4[i];
    }
    // stage Q then lift fragments
    {
        const int r = tid >> 1, cb = (tid & 1) * 32;
        const __half* qp = qh + ((size_t)(b * SS + m0 + r)) * AHSZ + h * HD + cb;
        uint4* dst = reinterpret_cast<uint4*>(&Qh[r * FQ_P + cb]);
#pragma unroll
        for (int u = 0; u < 4; u++) dst[u] = *reinterpret_cast<const uint4*>(qp + u * 8);
    }
    __syncthreads();

    unsigned Qa[4][4];
    {
        const unsigned q_lane = s2u(Qh) +
            (unsigned)(((w * 16 + (lane & 15)) * FQ_P + (lane >> 4) * 8) * 2);
#pragma unroll
        for (int kc = 0; kc < 4; kc++) ldsm4(Qa[kc], q_lane + (unsigned)(kc * 32));
    }
    __syncthreads();   // Q region about to be overwritten by K stages

    float o[8][4];
#pragma unroll
    for (int d = 0; d < 8; d++)
#pragma unroll
        for (int r = 0; r < 4; r++) o[d][r] = 0.f;
    float lacc0 = 0.f, lacc1 = 0.f;

    const __half* kbase = kh + (size_t)b * SS * AHSZ + h * HD;
    const __half* vbase = vh + (size_t)b * SS * AHSZ + h * HD;
    float* sco = scores + (size_t)z * SS * SS;

    const unsigned k_lane_b = s2u(Ksh) +
        (unsigned)((((lane & 15)) * FQ_P + (lane >> 4) * 8) * 2);
    const unsigned v_lane_b = s2u(Vsh) +
        (unsigned)((((lane & 7) + ((lane >> 3) & 1) * 8) * FQ_P + ((lane >> 3) >> 1) * 8) * 2);

    const int sr = tid >> 2, scb = (tid & 3) * 16;
    const unsigned k_st = s2u(Ksh) + (unsigned)((sr * FQ_P + scb) * 2);
    const unsigned v_st = s2u(Vsh) + (unsigned)((sr * FQ_P + scb) * 2);

    // prologue: stage kt=0
    {
        const __half* kp = kbase + (size_t)sr * AHSZ + scb;
        const __half* vp = vbase + (size_t)sr * AHSZ + scb;
        cpa16(k_st, kp);      cpa16(k_st + 16, kp + 8);
        cpa16(v_st, vp);      cpa16(v_st + 16, vp + 8);
        cpa_commit();
    }

    for (int kt = 0; kt < 32; kt++) {
        const int n0 = kt * 64;
        if (kt < 31) {
            const unsigned s = (unsigned)((kt + 1) & 1) * KV_STAGE;
            const __half* kp = kbase + (size_t)(n0 + 64 + sr) * AHSZ + scb;
            const __half* vp = vbase + (size_t)(n0 + 64 + sr) * AHSZ + scb;
            cpa16(k_st + s, kp);      cpa16(k_st + s + 16, kp + 8);
            cpa16(v_st + s, vp);      cpa16(v_st + s + 16, vp + 8);
            cpa_commit();
            cpa_wait<1>();
        } else {
            cpa_wait<0>();
        }
        __syncthreads();

        const unsigned s = (unsigned)(kt & 1) * KV_STAGE;
        const unsigned k_lane = k_lane_b + s;
        const unsigned v_lane = v_lane_b + s;

#pragma unroll
        for (int kg = 0; kg < 4; kg++) {       // 16-key groups
            // ---- S = Q K^T ----
            float c[2][4];
#pragma unroll
            for (int jj = 0; jj < 2; jj++)
#pragma unroll
                for (int r = 0; r < 4; r++) c[jj][r] = 0.f;
#pragma unroll
            for (int kc = 0; kc < 4; kc++) {
                unsigned kb[4];
                ldsm4(kb, k_lane + (unsigned)((kg * 16 * FQ_P + kc * 16) * 2));
                mma_f16(c[0], Qa[kc], kb[0], kb[2]);
                mma_f16(c[1], Qa[kc], kb[1], kb[3]);
            }

            // ---- epilogue: scale+mask, store scores, exp, repack ----
            unsigned pa[4];
#pragma unroll
            for (int jj = 0; jj < 2; jj++) {
                const int colL = kg * 16 + jj * 8 + 2 * lr;
                const float mk0 = msk[n0 + colL], mk1 = msk[n0 + colL + 1];
                const float s0 = c[jj][0] * 0.125f + mk0;
                const float s1 = c[jj][1] * 0.125f + mk1;
                const float s2 = c[jj][2] * 0.125f + mk0;
                const float s3 = c[jj][3] * 0.125f + mk1;
                *reinterpret_cast<float2*>(&sco[(size_t)(m0 + row0) * SS + n0 + colL]) =
                    make_float2(s0, s1);
                *reinterpret_cast<float2*>(&sco[(size_t)(m0 + row0 + 8) * SS + n0 + colL]) =
                    make_float2(s2, s3);
                const float p0 = __expf(s0), p1 = __expf(s1);
                const float p2 = __expf(s2), p3 = __expf(s3);
                lacc0 += p0 + p1;
                lacc1 += p2 + p3;
                pa[jj * 2 + 0] = pack_f16(p0, p1);
                pa[jj * 2 + 1] = pack_f16(p2, p3);
            }

            // ---- PV over these 16 keys ----
#pragma unroll
            for (int dp = 0; dp < 4; dp++) {
                unsigned vb[4];
                ldsm4t(vb, v_lane + (unsigned)((kg * 16 * FQ_P + dp * 16) * 2));
                mma_f16(o[2 * dp],     pa, vb[0], vb[1]);
                mma_f16(o[2 * dp + 1], pa, vb[2], vb[3]);
            }
        }
        __syncthreads();
    }

    // ---- normalize & write attn ----
    float l0 = lacc0, l1 = lacc1;
    l0 += __shfl_xor_sync(0xFFFFFFFFu, l0, 1);
    l0 += __shfl_xor_sync(0xFFFFFFFFu, l0, 2);
    l1 += __shfl_xor_sync(0xFFFFFFFFu, l1, 1);
    l1 += __shfl_xor_sync(0xFFFFFFFFu, l1, 2);
    const float inv0 = 1.f / l0, inv1 = 1.f / l1;

#pragma unroll
    for (int d = 0; d < 8; d++) {
        const int col = h * HD + d * 8 + 2 * lr;
        const size_t r0 = ((size_t)(b * SS + m0 + row0)) * AHSZ + col;
        const size_t r1 = ((size_t)(b * SS + m0 + row0 + 8)) * AHSZ + col;
        const float v0 = o[d][0] * inv0, v1 = o[d][1] * inv0;
        const float v2 = o[d][2] * inv1, v3 = o[d][3] * inv1;
        *reinterpret_cast<float2*>(&attn[r0]) = make_float2(v0, v1);
        *reinterpret_cast<float2*>(&attn[r1]) = make_float2(v2, v3);
        *reinterpret_cast<unsigned*>(&attnh[r0]) = pack_f16(v0, v1);
        *reinterpret_cast<unsigned*>(&attnh[r1]) = pack_f16(v2, v3);
    }
}

// ---------------- depthwise conv: smem-staged, 16 positions/block, fp16 in/out ----------------
#define DW_POS 16
__global__ void __launch_bounds__(384) dwconv_k(const __half* __restrict__ xh,
                                                const float* __restrict__ dwk)
{
    __shared__ __half hsm[(DW_POS + 8) * HIDC];
    const int s0 = blockIdx.x * DW_POS;
    const int b  = blockIdx.y;
    const int tid = threadIdx.x;

    // stage 24 rows of 768 halves (uint4 = 8 halves): 24*96 = 2304 chunks
    for (int idx = tid; idx < (DW_POS + 8) * (HIDC / 8); idx += 384) {
        const int row = idx / (HIDC / 8);
        const int cb  = (idx % (HIDC / 8)) * 8;
        const int sp  = s0 - 4 + row;
        uint4 val = make_uint4(0, 0, 0, 0);
        if (sp >= 0 && sp < SS)
            val = *reinterpret_cast<const uint4*>(&xh[((size_t)b * SS + sp) * HIDC + cb]);
        *reinterpret_cast<uint4*>(&hsm[row * HIDC + cb]) = val;
    }
    __syncthreads();

    const int c0 = tid * 2;
    float kw0[KW], kw1[KW];
#pragma unroll
    for (int tp = 0; tp < KW; tp++) {
        kw0[tp] = dwk[c0 * KW + tp];
        kw1[tp] = dwk[(c0 + 1) * KW + tp];
    }

    for (int ls = 0; ls < DW_POS; ls++) {
        float a0 = 0.f, a1 = 0.f;
#pragma unroll
        for (int tp = 0; tp < KW; tp++) {
            const float2 xv = __half22float2(
                *reinterpret_cast<const __half2*>(&hsm[(ls + tp) * HIDC + c0]));
            a0 += xv.x * kw0[tp];
            a1 += xv.y * kw1[tp];
        }
        *reinterpret_cast<__half2*>(&g_dwh[((size_t)b * SS + s0 + ls) * HIDC + c0]) =
            __floats2half2_rn(a0, a1);
    }
}

// ---------------- tap softmax + windowed value conv: smem-staged, 16 positions/block ----------------
#define CO_POS 16
__global__ void __launch_bounds__(384) convout_k()
{
    __shared__ float vsm[(CO_POS + 8) * AHSZ];
    __shared__ float filt[CO_POS][HK + 2];
    const int s0 = blockIdx.x * CO_POS;
    const int b  = blockIdx.y;
    const int tid = threadIdx.x;

    // stage 24 rows of 384 floats (float4): 24*96 = 2304 chunks
    for (int idx = tid; idx < (CO_POS + 8) * (AHSZ / 4); idx += 384) {
        const int row = idx / (AHSZ / 4);
        const int cb  = (idx % (AHSZ / 4)) * 4;
        const int sp  = s0 - 4 + row;
        float4 val = make_float4(0.f, 0.f, 0.f, 0.f);
        if (sp >= 0 && sp < SS)
            val = *reinterpret_cast<const float4*>(&g_v[((size_t)b * SS + sp) * AHSZ + cb]);
        *reinterpret_cast<float4*>(&vsm[row * AHSZ + cb]) = val;
    }

    // tap softmax: 96 threads, each one (ls, h)
    if (tid < CO_POS * NH) {
        const int ls = tid % CO_POS, h = tid / CO_POS;
        const size_t mrow = (size_t)(b * SS + s0 + ls) * HK + h * KW;
        float lg[KW];
        float mx = -1e30f;
#pragma unroll
        for (int i = 0; i < KW; i++) {
            lg[i] = g_logits[mrow + i];
            mx = fmaxf(mx, lg[i]);
        }
        float sum = 0.f;
#pragma unroll
        for (int i = 0; i < KW; i++) { lg[i] = __expf(lg[i] - mx); sum += lg[i]; }
        const float is = 1.f / sum;
#pragma unroll
        for (int i = 0; i < KW; i++) filt[ls][h * KW + i] = lg[i] * is;
    }
    __syncthreads();

    const int c = tid;
    const int hb = (c >> 6) * KW;
    for (int ls = 0; ls < CO_POS; ls++) {
        float acc = 0.f;
#pragma unroll
        for (int tp = 0; tp < KW; tp++)
            acc += vsm[(ls + tp) * AHSZ + c] * filt[ls][hb + tp];
        g_convh[((size_t)(b * SS + s0 + ls)) * AHSZ + c] = __float2half(acc);
    }
}

// ---------------- launch ----------------
extern "C" void kernel_launch(void* const* d_in, const int* in_sizes, int n_in,
                              void* d_out, int out_size)
{
    const float* hidden = (const float*)d_in[0];
    const float* amask  = (const float*)d_in[1];
    const float* Wq = (const float*)d_in[2];  const float* bq = (const float*)d_in[3];
    const float* Wk = (const float*)d_in[4];  const float* bk = (const float*)d_in[5];
    const float* Wv = (const float*)d_in[6];  const float* bv = (const float*)d_in[7];
    const float* dwk = (const float*)d_in[8];
    const float* pw  = (const float*)d_in[9]; const float* sepb = (const float*)d_in[10];
    const float* Wak = (const float*)d_in[11]; const float* bak = (const float*)d_in[12];
    const float* Wsl = (const float*)d_in[13]; const float* bsl = (const float*)d_in[14];
    const float* Wcl = (const float*)d_in[15]; const float* bcl = (const float*)d_in[16];

    __half *hidh, *qhp, *khp, *vhp, *dwh, *convh, *attnh;
    __half *wqh, *wkh, *wvh, *pwth, *wslh, *wclh, *wakh;
    float *qf, *vf, *ks, *lg, *attn_fb, *sco_fb;
    cudaGetSymbolAddress((void**)&hidh,  g_hidden_h);
    cudaGetSymbolAddress((void**)&qhp,   g_qh);
    cudaGetSymbolAddress((void**)&khp,   g_kh);
    cudaGetSymbolAddress((void**)&vhp,   g_vh);
    cudaGetSymbolAddress((void**)&qf,    g_q);
    cudaGetSymbolAddress((void**)&vf,    g_v);
    cudaGetSymbolAddress((void**)&dwh,   g_dwh);
    cudaGetSymbolAddress((void**)&ks,    g_ks);
    cudaGetSymbolAddress((void**)&convh, g_convh);
    cudaGetSymbolAddress((void**)&lg,    g_logits);
    cudaGetSymbolAddress((void**)&attnh, g_attn_h);
    cudaGetSymbolAddress((void**)&wqh,   g_Wq_h);
    cudaGetSymbolAddress((void**)&wkh,   g_Wk_h);
    cudaGetSymbolAddress((void**)&wvh,   g_Wv_h);
    cudaGetSymbolAddress((void**)&pwth,  g_pwt_h);
    cudaGetSymbolAddress((void**)&wslh,  g_Wsl_h);
    cudaGetSymbolAddress((void**)&wclh,  g_Wcl_h);
    cudaGetSymbolAddress((void**)&wakh,  g_Wak_h);
    cudaGetSymbolAddress((void**)&attn_fb, g_attn_fb);
    cudaGetSymbolAddress((void**)&sco_fb,  g_sco_fb);

    float* outp = (float*)d_out;
    const size_t CTX_SZ = (size_t)MROWS * HIDC;
    const size_t ATT_OFF = CTX_SZ;
    const size_t ATT_SZ  = (size_t)MROWS * AHSZ;
    const size_t SCO_OFF = ATT_OFF + ATT_SZ;
    const size_t SCO_SZ  = (size_t)NZ * SS * SS;
    float* attnp = ((size_t)out_size >= ATT_OFF + ATT_SZ) ? outp + ATT_OFF : attn_fb;
    float* scop  = ((size_t)out_size >= SCO_OFF + SCO_SZ) ? outp + SCO_OFF : sco_fb;

    // ---- prep: fp16 conversions ----
    cvt_h<<<(MROWS * HIDC / 4 + 255) / 256, 256>>>((const float4*)hidden, (__half2*)hidh, MROWS * HIDC / 4);
    cvt_h<<<(HIDC * AHSZ / 4 + 255) / 256, 256>>>((const float4*)Wq, (__half2*)wqh, HIDC * AHSZ / 4);
    cvt_h<<<(HIDC * AHSZ / 4 + 255) / 256, 256>>>((const float4*)Wk, (__half2*)wkh, HIDC * AHSZ / 4);
    cvt_h<<<(HIDC * AHSZ / 4 + 255) / 256, 256>>>((const float4*)Wv, (__half2*)wvh, HIDC * AHSZ / 4);
    cvt_h<<<(AHSZ * AHSZ / 4 + 255) / 256, 256>>>((const float4*)Wsl, (__half2*)wslh, AHSZ * AHSZ / 4);
    cvt_h<<<(AHSZ * AHSZ / 4 + 255) / 256, 256>>>((const float4*)Wcl, (__half2*)wclh, AHSZ * AHSZ / 4);
    transpose_pw<<<dim3(HIDC / 32, AHSZ / 32), dim3(32, 8)>>>(pw, pwth);
    pad_wak<<<AHSZ, 64>>>(Wak, wakh);

    const dim3 blk(256);

    // 1) fused QKV (fp16, double-buffered)
    hgemm<H_QKV><<<dim3(AHSZ / 64, MROWS / 128, 3), blk>>>(
        hidh, nullptr,
        wqh, wkh, wvh, bq, bk, bv,
        qf, nullptr, vf, qhp, khp, vhp,
        HIDC, HIDC, AHSZ, AHSZ);

    // 2) fused attention (fp16, K/V double-buffered via cp.async)
    {
        cudaFuncSetAttribute(fattn_k, cudaFuncAttributeMaxDynamicSharedMemorySize, FA_SMEM_B);
        fattn_k<<<dim3(SS / 128, NZ), 256, FA_SMEM_B>>>(qhp, khp, vhp, amask, scop, attnp, attnh);
    }

    // 3) depthwise conv (smem-staged, fp16)
    dwconv_k<<<dim3(SS / DW_POS, BB), 384>>>(hidh, dwk);

    // 4) pointwise: ks = dw @ pw^T + sep_bias
    hgemm<H_NT><<<dim3(AHSZ / 64, MROWS / 128, 1), blk>>>(
        dwh, nullptr,
        pwth, nullptr, nullptr, sepb, nullptr, nullptr,
        ks, nullptr, nullptr, nullptr, nullptr, nullptr,
        HIDC, HIDC, AHSZ, AHSZ);

    // 5) filter logits: (ks*q) @ Wak + bak
    hgemm_filt<<<dim3(1, MROWS / 128), blk>>>(ks, qf, wakh, bak, lg);

    // 6) tap softmax + windowed value conv (smem-staged)
    convout_k<<<dim3(SS / CO_POS, BB), 384>>>();

    // 7) fused mix: context = [attn@Wsl+bsl | conv@Wcl+bcl]
    hgemm<H_MIX><<<dim3(AHSZ / 64, MROWS / 128, 2), blk>>>(
        attnh, convh,
        wslh, wclh, nullptr, bsl, bcl, nullptr,
        outp, nullptr, nullptr, nullptr, nullptr, nullptr,
        AHSZ, AHSZ, AHSZ, HIDC);
}